// round 14
// baseline (speedup 1.0000x reference)
#include <cuda_runtime.h>
#include <cuda_fp16.h>
#include <math.h>
#include <stdint.h>

#define N_   1024
#define R_   100
#define D_   256
#define T_   14
#define H_   8
#define MM_  600
#define OBJ_ 36
#define PLN_ 16
#define DH_  32
#define NR_  (N_*R_)   /* 102400 */
#define KP3  768       /* 3-term fp16 split K' = 3*D */

// ---------------- scratch (device globals; no runtime allocation) ----------------
__device__ float g_beff[3*D_];
__device__ float g_qkv[(size_t)NR_*3*D_];
__device__ float g_inter[(size_t)NR_*D_];
__device__ float g_x0[(size_t)NR_*MM_];
__device__ float g_x1[(size_t)N_*MM_];
__device__ float g_qpool[(size_t)N_*D_];
__device__ __half g_vh[(size_t)NR_*KP3];
__device__ __half g_attnh[(size_t)NR_*KP3];
__device__ __half g_interh[(size_t)NR_*KP3];
__device__ __half g_Wqkvh[(size_t)(3*D_)*KP3];
__device__ __half g_Woh[(size_t)D_*KP3];
__device__ __half g_Wx0h[(size_t)768*KP3];

// ---------------- helpers ----------------
__device__ __forceinline__ float blockReduceSum(float v, float* red, int nthr) {
    int t = threadIdx.x;
    red[t] = v; __syncthreads();
    for (int s = nthr >> 1; s > 0; s >>= 1) {
        if (t < s) red[t] += red[t + s];
        __syncthreads();
    }
    float r = red[0]; __syncthreads();
    return r;
}

__device__ __forceinline__ uint32_t smem_u32(const void* p) {
    return (uint32_t)__cvta_generic_to_shared(p);
}

__device__ __forceinline__ void split_f16(float x, __half& hi, __half& lo) {
    hi = __float2half_rn(x);
    lo = __float2half_rn(x - __half2float(hi));
}

__device__ __forceinline__ void ldsm4(uint32_t* r, uint32_t addr) {
    asm volatile("ldmatrix.sync.aligned.m8n8.x4.shared.b16 {%0,%1,%2,%3}, [%4];"
                 : "=r"(r[0]), "=r"(r[1]), "=r"(r[2]), "=r"(r[3]) : "r"(addr));
}

__device__ __forceinline__ void mma16816(float* d, const uint32_t* a,
                                         uint32_t b0, uint32_t b1) {
    asm volatile(
        "mma.sync.aligned.m16n8k16.row.col.f32.f16.f16.f32 "
        "{%0,%1,%2,%3}, {%4,%5,%6,%7}, {%8,%9}, {%0,%1,%2,%3};"
        : "+f"(d[0]), "+f"(d[1]), "+f"(d[2]), "+f"(d[3])
        : "r"(a[0]), "r"(a[1]), "r"(a[2]), "r"(a[3]), "r"(b0), "r"(b1));
}

__device__ __forceinline__ void cp16(uint32_t dst, const void* src) {
    asm volatile("cp.async.cg.shared.global [%0], [%1], 16;"
                 :: "r"(dst), "l"(src));
}
__device__ __forceinline__ void cp_commit() {
    asm volatile("cp.async.commit_group;");
}

// ---------------- weight fusion: Weff = in_w_part @ W_part -> fp16 split [hi|lo|hi]
__global__ void fusew_kernel(const float* __restrict__ in_w,
                             const float* __restrict__ Wq,
                             const float* __restrict__ Wk,
                             const float* __restrict__ Wv,
                             __half* __restrict__ Wh) {
    int p = blockIdx.z;
    const float* W = (p == 0) ? Wq : ((p == 1) ? Wk : Wv);
    __shared__ float Ai[16][16];
    __shared__ float Bi[16][17];
    int tx = threadIdx.x, ty = threadIdx.y;
    int o = blockIdx.y * 16 + ty;
    int k = blockIdx.x * 16 + tx;
    float acc = 0.f;
    for (int j0 = 0; j0 < D_; j0 += 16) {
        Ai[ty][tx] = in_w[(size_t)(p*D_ + o)*D_ + j0 + tx];
        Bi[ty][tx] = W[(size_t)(j0 + ty)*D_ + k];
        __syncthreads();
        #pragma unroll
        for (int jj = 0; jj < 16; jj++) acc += Ai[ty][jj] * Bi[jj][tx];
        __syncthreads();
    }
    __half hi, lo;
    split_f16(acc, hi, lo);
    __half* yr = Wh + (size_t)(p*D_ + o) * KP3;
    yr[k] = hi; yr[D_ + k] = lo; yr[2*D_ + k] = hi;
}

__global__ void fuseb_kernel(const float* __restrict__ in_w,
                             const float* __restrict__ in_b,
                             const float* __restrict__ bq,
                             const float* __restrict__ bk,
                             const float* __restrict__ bv,
                             float* __restrict__ beff) {
    int o = blockIdx.x * blockDim.x + threadIdx.x;
    if (o >= 3*D_) return;
    int p = o / D_;
    const float* bb = (p == 0) ? bq : ((p == 1) ? bk : bv);
    const float* wrow = in_w + (size_t)o * D_;
    float s = in_b[o];
    for (int j = 0; j < D_; j++) s += wrow[j] * bb[j];
    beff[o] = s;
}

// ---------------- activation split: [hi|hi|lo] ----------------
__global__ __launch_bounds__(128) void asplit_kernel(const float* __restrict__ X,
                                                     __half* __restrict__ Y) {
    size_t row = blockIdx.x;
    int k = threadIdx.x * 2;
    float2 v = *(const float2*)(X + row * D_ + k);
    __half h0, l0, h1, l1;
    split_f16(v.x, h0, l0);
    split_f16(v.y, h1, l1);
    __half2 hp; hp.x = h0; hp.y = h1;
    __half2 lp; lp.x = l0; lp.y = l1;
    __half2* yr = (__half2*)(Y + row * KP3);
    int o = k >> 1;
    yr[o] = hp;
    yr[(D_ >> 1) + o] = hp;
    yr[D_ + o] = lp;
}

// ---------------- weight split: [hi|lo|hi] ----------------
__global__ __launch_bounds__(128) void wsplit_kernel(const float* __restrict__ W,
                                                     __half* __restrict__ Y, int Nc) {
    int r = blockIdx.x;
    int k = threadIdx.x * 2;
    float2 v = make_float2(0.f, 0.f);
    if (r < Nc) v = *(const float2*)(W + (size_t)r * D_ + k);
    __half h0, l0, h1, l1;
    split_f16(v.x, h0, l0);
    split_f16(v.y, h1, l1);
    __half2 hp; hp.x = h0; hp.y = h1;
    __half2 lp; lp.x = l0; lp.y = l1;
    __half2* yr = (__half2*)(Y + (size_t)r * KP3);
    int o = k >> 1;
    yr[o] = hp;
    yr[(D_ >> 1) + o] = lp;
    yr[D_ + o] = hp;
}

// ---------------- HMMA GEMM: C[M,Nc] f32 = A[M,768] * B[Ncpad,768]^T + bias ------
// 128x128 tile, BK=32, 128 threads (4 warps as 2m x 2n, 64x64 per warp),
// 3-stage cp.async pipeline, 24 k-blocks.
#define SROW   40                        /* padded row stride in halves (80 B) */
#define STGH   (2 * 128 * SROW)          /* halves per stage (A tile + B tile) */
#define NSTAGE 3
#define GSMEM  (NSTAGE * STGH * 2)       /* 61440 bytes */

__global__ __launch_bounds__(128, 2) void gemm_mma(const __half* __restrict__ A,
                                                   const __half* __restrict__ B,
                                                   const float* __restrict__ bias,
                                                   float* __restrict__ C, int Nc) {
    extern __shared__ __half smem[];
    int tid = threadIdx.x;
    int wid = tid >> 5, lane = tid & 31;
    int wm = wid & 1, wn = wid >> 1;
    int m0 = blockIdx.y * 128, n0 = blockIdx.x * 128;

    // loaders: thread t owns row t of both tiles (32 halves = 64 B = 4x cp16)
    const __half* Ag = A + (size_t)(m0 + tid) * KP3;
    const __half* Bg = B + (size_t)(n0 + tid) * KP3;
    uint32_t sdstA = smem_u32(smem) + (uint32_t)(tid * SROW) * 2;
    uint32_t sdstB = sdstA + 128 * SROW * 2;

    float acc[4][8][4];
    #pragma unroll
    for (int i = 0; i < 4; i++)
        #pragma unroll
        for (int j = 0; j < 8; j++)
            #pragma unroll
            for (int q = 0; q < 4; q++) acc[i][j][q] = 0.f;

    // prologue: issue stages 0..NSTAGE-2
    #pragma unroll
    for (int s = 0; s < NSTAGE - 1; s++) {
        uint32_t so = (uint32_t)(s * STGH) * 2;
        const __half* As = Ag + s * 32;
        const __half* Bs = Bg + s * 32;
        #pragma unroll
        for (int q = 0; q < 4; q++) {
            cp16(sdstA + so + q*16, As + q*8);
            cp16(sdstB + so + q*16, Bs + q*8);
        }
        cp_commit();
    }

    int arow = wm*64 + (lane & 15);
    int brow = wn*64 + (lane & 15);
    int colb = (lane >> 4) * 8;
    uint32_t sbaseA = smem_u32(smem);
    uint32_t sbaseB = sbaseA + 128 * SROW * 2;

    for (int kb = 0; kb < 24; kb++) {
        int pf = kb + NSTAGE - 1;
        if (pf < 24) {
            uint32_t so = (uint32_t)((pf % NSTAGE) * STGH) * 2;
            const __half* As = Ag + pf * 32;
            const __half* Bs = Bg + pf * 32;
            #pragma unroll
            for (int q = 0; q < 4; q++) {
                cp16(sdstA + so + q*16, As + q*8);
                cp16(sdstB + so + q*16, Bs + q*8);
            }
        }
        cp_commit();
        asm volatile("cp.async.wait_group %0;" :: "n"(NSTAGE - 1));
        __syncthreads();

        uint32_t so = (uint32_t)((kb % NSTAGE) * STGH) * 2;
        #pragma unroll
        for (int ks = 0; ks < 2; ks++) {
            uint32_t af[4][4], bfr[4][4];
            #pragma unroll
            for (int mi = 0; mi < 4; mi++)
                ldsm4(af[mi], sbaseA + so +
                      (uint32_t)((arow + mi*16)*SROW + ks*16 + colb) * 2);
            #pragma unroll
            for (int ni = 0; ni < 4; ni++)
                ldsm4(bfr[ni], sbaseB + so +
                      (uint32_t)((brow + ni*16)*SROW + ks*16 + colb) * 2);
            #pragma unroll
            for (int mi = 0; mi < 4; mi++) {
                #pragma unroll
                for (int ni = 0; ni < 4; ni++) {
                    mma16816(acc[mi][2*ni],   af[mi], bfr[ni][0], bfr[ni][2]);
                    mma16816(acc[mi][2*ni+1], af[mi], bfr[ni][1], bfr[ni][3]);
                }
            }
        }
        __syncthreads();
    }

    // epilogue
    int rbase = m0 + wm*64 + (lane >> 2);
    int cbase = n0 + wn*64 + (lane & 3)*2;
    #pragma unroll
    for (int mi = 0; mi < 4; mi++) {
        #pragma unroll
        for (int nj = 0; nj < 8; nj++) {
            int r = rbase + mi*16;
            int c = cbase + nj*8;
            if (c < Nc) {
                float b0v = bias[c];
                C[(size_t)r * Nc + c]       = acc[mi][nj][0] + b0v;
                C[(size_t)(r+8) * Nc + c]   = acc[mi][nj][2] + b0v;
            }
            if (c + 1 < Nc) {
                float b1v = bias[c+1];
                C[(size_t)r * Nc + c + 1]     = acc[mi][nj][1] + b1v;
                C[(size_t)(r+8) * Nc + c + 1] = acc[mi][nj][3] + b1v;
            }
        }
    }
}

// ---------------- SIMT SGEMM (tiny x1) ----------------
__global__ __launch_bounds__(256) void sgemm_bt(const float* __restrict__ A,
                                                const float* __restrict__ B,
                                                const float* __restrict__ bias,
                                                float* __restrict__ C,
                                                int M, int Nc, int K) {
    __shared__ float As[2][16][128];
    __shared__ float Bs[2][16][128];
    int tid = threadIdx.x;
    int tcol = tid & 15, trow = tid >> 4;
    int lRow = tid >> 1;
    int lCol = (tid & 1) * 8;
    const float* Ab = A + ((size_t)blockIdx.y * 128 + lRow) * K + lCol;
    int bRowG = blockIdx.x * 128 + lRow;
    const float* Bb = B + (size_t)bRowG * K + lCol;
    bool bvalid = (bRowG < Nc);

    float acc[8][8];
    #pragma unroll
    for (int i = 0; i < 8; i++)
        #pragma unroll
        for (int j = 0; j < 8; j++) acc[i][j] = 0.f;

    float4 a0, a1, b0, b1;
    const float4 z4 = make_float4(0.f, 0.f, 0.f, 0.f);
    a0 = *(const float4*)(Ab);
    a1 = *(const float4*)(Ab + 4);
    b0 = bvalid ? *(const float4*)(Bb)     : z4;
    b1 = bvalid ? *(const float4*)(Bb + 4) : z4;
    As[0][lCol+0][lRow] = a0.x; As[0][lCol+1][lRow] = a0.y;
    As[0][lCol+2][lRow] = a0.z; As[0][lCol+3][lRow] = a0.w;
    As[0][lCol+4][lRow] = a1.x; As[0][lCol+5][lRow] = a1.y;
    As[0][lCol+6][lRow] = a1.z; As[0][lCol+7][lRow] = a1.w;
    Bs[0][lCol+0][lRow] = b0.x; Bs[0][lCol+1][lRow] = b0.y;
    Bs[0][lCol+2][lRow] = b0.z; Bs[0][lCol+3][lRow] = b0.w;
    Bs[0][lCol+4][lRow] = b1.x; Bs[0][lCol+5][lRow] = b1.y;
    Bs[0][lCol+6][lRow] = b1.z; Bs[0][lCol+7][lRow] = b1.w;
    __syncthreads();

    int buf = 0;
    for (int k0 = 0; k0 < K; k0 += 16) {
        bool hn = (k0 + 16 < K);
        if (hn) {
            a0 = *(const float4*)(Ab + k0 + 16);
            a1 = *(const float4*)(Ab + k0 + 20);
            b0 = bvalid ? *(const float4*)(Bb + k0 + 16) : z4;
            b1 = bvalid ? *(const float4*)(Bb + k0 + 20) : z4;
        }
        #pragma unroll
        for (int kk = 0; kk < 16; kk++) {
            float ar[8], br[8];
            *(float4*)(ar)     = *(const float4*)&As[buf][kk][trow*8];
            *(float4*)(ar + 4) = *(const float4*)&As[buf][kk][trow*8 + 4];
            *(float4*)(br)     = *(const float4*)&Bs[buf][kk][tcol*8];
            *(float4*)(br + 4) = *(const float4*)&Bs[buf][kk][tcol*8 + 4];
            #pragma unroll
            for (int i = 0; i < 8; i++)
                #pragma unroll
                for (int j = 0; j < 8; j++) acc[i][j] += ar[i] * br[j];
        }
        if (hn) {
            int nb = buf ^ 1;
            As[nb][lCol+0][lRow] = a0.x; As[nb][lCol+1][lRow] = a0.y;
            As[nb][lCol+2][lRow] = a0.z; As[nb][lCol+3][lRow] = a0.w;
            As[nb][lCol+4][lRow] = a1.x; As[nb][lCol+5][lRow] = a1.y;
            As[nb][lCol+6][lRow] = a1.z; As[nb][lCol+7][lRow] = a1.w;
            Bs[nb][lCol+0][lRow] = b0.x; Bs[nb][lCol+1][lRow] = b0.y;
            Bs[nb][lCol+2][lRow] = b0.z; Bs[nb][lCol+3][lRow] = b0.w;
            Bs[nb][lCol+4][lRow] = b1.x; Bs[nb][lCol+5][lRow] = b1.y;
            Bs[nb][lCol+6][lRow] = b1.z; Bs[nb][lCol+7][lRow] = b1.w;
            __syncthreads();
            buf = nb;
        }
    }

    int rb = blockIdx.y * 128 + trow * 8;
    int cb = blockIdx.x * 128 + tcol * 8;
    for (int i = 0; i < 8; i++) {
        size_t ro = (size_t)(rb + i) * Nc;
        #pragma unroll
        for (int j = 0; j < 8; j++) {
            int c = cb + j;
            if (c < Nc) C[ro + c] = acc[i][j] + bias[c];
        }
    }
}

// ---------------- attention ----------------
__global__ __launch_bounds__(64) void attn_kernel(const float* __restrict__ qkv,
                                                  __half* __restrict__ outh) {
    __shared__ float Ks[R_][DH_];
    __shared__ float Vs[R_][DH_];
    int b = blockIdx.x;
    int n = b >> 3, h = b & 7;
    const float* base = qkv + (size_t)n * R_ * (3*D_) + h * DH_;
    for (int t = threadIdx.x; t < R_ * 8; t += 64) {
        int r = t >> 3, c = (t & 7) * 4;
        const float* p = base + (size_t)r * (3*D_) + c;
        *(float4*)&Ks[r][c] = *(const float4*)(p + D_);
        *(float4*)&Vs[r][c] = *(const float4*)(p + 2*D_);
    }
    __syncthreads();

    int t = threadIdx.x;
    if (t < 50) {
        const float scale = 0.17677669529663687f;  // 1/sqrt(32)
        int r0 = t, r1 = t + 50;
        float q0[DH_], q1[DH_];
        const float* p0 = base + (size_t)r0 * (3*D_);
        const float* p1 = base + (size_t)r1 * (3*D_);
        #pragma unroll
        for (int d = 0; d < DH_; d += 4) {
            float4 v0 = *(const float4*)(p0 + d);
            float4 v1 = *(const float4*)(p1 + d);
            q0[d+0] = v0.x * scale; q0[d+1] = v0.y * scale;
            q0[d+2] = v0.z * scale; q0[d+3] = v0.w * scale;
            q1[d+0] = v1.x * scale; q1[d+1] = v1.y * scale;
            q1[d+2] = v1.z * scale; q1[d+3] = v1.w * scale;
        }
        float acc0[DH_], acc1[DH_];
        #pragma unroll
        for (int d = 0; d < DH_; d++) { acc0[d] = 0.f; acc1[d] = 0.f; }
        float s0 = 0.f, s1 = 0.f;
        for (int k = 0; k < R_; k++) {
            float d0 = 0.f, d1 = 0.f;
            #pragma unroll
            for (int d = 0; d < DH_; d++) {
                float kv = Ks[k][d];
                d0 += q0[d] * kv;
                d1 += q1[d] * kv;
            }
            float w0 = __expf(d0), w1 = __expf(d1);
            s0 += w0; s1 += w1;
            #pragma unroll
            for (int d = 0; d < DH_; d++) {
                float vv = Vs[k][d];
                acc0[d] += w0 * vv;
                acc1[d] += w1 * vv;
            }
        }
        float i0 = 1.f / s0, i1 = 1.f / s1;
        __half2* ob0 = (__half2*)(outh + (size_t)(n * R_ + r0) * KP3 + h * DH_);
        __half2* ob1 = (__half2*)(outh + (size_t)(n * R_ + r1) * KP3 + h * DH_);
        #pragma unroll
        for (int d = 0; d < DH_; d += 2) {
            float xa = acc0[d] * i0, xb = acc0[d+1] * i0;
            float ya = acc1[d] * i1, yb = acc1[d+1] * i1;
            __half ha0, la0, hb0, lb0, ha1, la1, hb1, lb1;
            split_f16(xa, ha0, la0); split_f16(xb, hb0, lb0);
            split_f16(ya, ha1, la1); split_f16(yb, hb1, lb1);
            __half2 h2a; h2a.x = ha0; h2a.y = hb0;
            __half2 l2a; l2a.x = la0; l2a.y = lb0;
            __half2 h2b; h2b.x = ha1; h2b.y = hb1;
            __half2 l2b; l2b.x = la1; l2b.y = lb1;
            int o = d >> 1;
            ob0[o] = h2a; ob0[(D_ >> 1) + o] = h2a; ob0[D_ + o] = l2a;
            ob1[o] = h2b; ob1[(D_ >> 1) + o] = h2b; ob1[D_ + o] = l2b;
        }
    }
}

// ---------------- layernorm ----------------
__global__ __launch_bounds__(256) void ln_kernel(const float* __restrict__ X,
                                                 const float* __restrict__ g,
                                                 const float* __restrict__ b,
                                                 __half* __restrict__ Yh) {
    __shared__ float red[256];
    int row = blockIdx.x, t = threadIdx.x;
    float v = X[(size_t)row * D_ + t];
    float mu = blockReduceSum(v, red, 256) * (1.f / D_);
    float d = v - mu;
    float var = blockReduceSum(d * d, red, 256) * (1.f / D_);
    float y = d * rsqrtf(var + 1e-5f) * g[t] + b[t];
    __half hi, lo;
    split_f16(y, hi, lo);
    __half* yr = Yh + (size_t)row * KP3;
    yr[t] = hi; yr[D_ + t] = hi; yr[2*D_ + t] = lo;
}

// ---------------- question pool ----------------
__global__ void qpool_kernel(const float* __restrict__ q_emb, float* __restrict__ qp) {
    int n = blockIdx.x, d = threadIdx.x;
    float s = 0.f;
    for (int tt = 0; tt < T_; tt++) s += q_emb[((size_t)n * T_ + tt) * D_ + d];
    qp[(size_t)n * D_ + d] = s * (1.f / T_);
}

// ---------------- MLB finalize ----------------
__global__ __launch_bounds__(128) void mlb_kernel(const float* __restrict__ x0,
                                                  const float* __restrict__ x1,
                                                  const float* __restrict__ lo_w,
                                                  const float* __restrict__ lo_b,
                                                  float* __restrict__ scores) {
    __shared__ float red[128];
    int nr = blockIdx.x;
    int n = nr / R_;
    const float* a = x0 + (size_t)nr * MM_;
    const float* bv = x1 + (size_t)n * MM_;
    float s_abs = 0.f, s_dot = 0.f;
    for (int j = threadIdx.x; j < MM_; j += 128) {
        float z = a[j] * bv[j];
        float az = fabsf(z);
        float ss = copysignf(sqrtf(az), z);
        s_abs += az;
        s_dot += ss * lo_w[j];
    }
    s_abs = blockReduceSum(s_abs, red, 128);
    s_dot = blockReduceSum(s_dot, red, 128);
    if (threadIdx.x == 0) {
        float nrm = fmaxf(sqrtf(s_abs), 1e-12f);
        float val = s_dot / nrm + lo_b[0];
        scores[nr] = 1.f / (1.f + __expf(-val));
    }
}

// ---------------- counter ----------------
__device__ __forceinline__ float plin2(const float* __restrict__ w,
                                       const float* __restrict__ c, float x) {
    float y = 16.f * __saturatef(x);
    float fl = floorf(y);
    int i = (int)fl; if (i > 16) i = 16; if (i < 0) i = 0;
    float fr = y - fl;
    int i1 = i + 1; if (i1 > 16) i1 = 16;
    return c[i] + fr * w[i1];
}

__global__ __launch_bounds__(128) void counter_kernel(const float* __restrict__ scores,
                                                      const float* __restrict__ boxes,
                                                      const float* __restrict__ pw,
                                                      float* __restrict__ pred,
                                                      float* __restrict__ confp) {
    __shared__ float satt[R_];
    __shared__ float rv[128];
    __shared__ int   ri[128];
    __shared__ float pwW[8][PLN_+1], pwC[8][PLN_+1];
    __shared__ float att_top[OBJ_], bx[OBJ_][4], area[OBJ_];
    __shared__ float dist[OBJ_][OBJ_], dsc[OBJ_][OBJ_], scm[OBJ_][OBJ_], simm[OBJ_][OBJ_];
    __shared__ float rs[OBJ_];
    __shared__ float red[128];
    __shared__ float bc[3];

    int n = blockIdx.x, t = threadIdx.x;
    if (t < R_) satt[t] = scores[(size_t)n * R_ + t];
    if (t < 8) {
        float tmp[PLN_+1]; float sum = 0.f;
        for (int j = 0; j <= PLN_; j++) {
            float a = fabsf(pw[t*(PLN_+1) + j]);
            if (j == 0) a = 0.f;
            tmp[j] = a; sum += a;
        }
        float inv = 1.f / sum, c = 0.f;
        for (int j = 0; j <= PLN_; j++) {
            float wj = tmp[j] * inv;
            pwW[t][j] = wj; c += wj; pwC[t][j] = c;
        }
    }
    __syncthreads();

    for (int it = 0; it < OBJ_; it++) {
        float bvv = -1e30f; int bii = -1;
        if (t < R_) { bvv = satt[t]; bii = t; }
        rv[t] = bvv; ri[t] = bii; __syncthreads();
        for (int s = 64; s > 0; s >>= 1) {
            if (t < s) {
                float ov = rv[t+s]; int oi = ri[t+s];
                if (ov > rv[t] || (ov == rv[t] && oi >= 0 && (ri[t] < 0 || oi < ri[t]))) {
                    rv[t] = ov; ri[t] = oi;
                }
            }
            __syncthreads();
        }
        if (t == 0) {
            int id = ri[0];
            att_top[it] = rv[0];
            satt[id] = -1e30f;
            const float* bp = boxes + ((size_t)n * R_ + id) * 4;
            bx[it][0] = bp[0]; bx[it][1] = bp[1]; bx[it][2] = bp[2]; bx[it][3] = bp[3];
        }
        __syncthreads();
    }

    if (t < OBJ_)
        area[t] = fmaxf(bx[t][2]-bx[t][0], 0.f) * fmaxf(bx[t][3]-bx[t][1], 0.f);
    __syncthreads();

    for (int u = t; u < OBJ_*OBJ_; u += 128) {
        int j = u / OBJ_, k = u % OBJ_;
        float xx1 = fmaxf(bx[j][0], bx[k][0]), yy1 = fmaxf(bx[j][1], bx[k][1]);
        float xx2 = fminf(bx[j][2], bx[k][2]), yy2 = fminf(bx[j][3], bx[k][3]);
        float iw = fmaxf(xx2-xx1, 0.f), ih = fmaxf(yy2-yy1, 0.f);
        float inter = iw * ih;
        float iou = inter / (area[j] + area[k] - inter + 1e-12f);
        float dd = 1.f - iou;
        dist[j][k] = dd;
        float rel = att_top[j] * att_top[k];
        scm[j][k] = plin2(pwW[0], pwC[0], rel) * plin2(pwW[1], pwC[1], dd);
        dsc[j][k] = plin2(pwW[3], pwC[3], rel) * plin2(pwW[4], pwC[4], dd);
    }
    __syncthreads();

    for (int u = t; u < OBJ_*OBJ_; u += 128) {
        int j = u / OBJ_, k = u % OBJ_;
        float p = plin2(pwW[2], pwC[2], 1.f - fabsf(att_top[j] - att_top[k]));
        #pragma unroll 4
        for (int i = 0; i < OBJ_; i++)
            p *= plin2(pwW[2], pwC[2], 1.f - fabsf(dsc[i][j] - dsc[i][k]));
        simm[j][k] = p;
    }
    __syncthreads();

    if (t < OBJ_) {
        float s = 0.f;
        for (int k = 0; k < OBJ_; k++) s += simm[t][k];
        rs[t] = s;
    }
    __syncthreads();

    float loc_tot = 0.f, loc_conf = 0.f;
    for (int u = t; u < OBJ_*OBJ_; u += 128) {
        int j = u / OBJ_, k = u % OBJ_;
        loc_tot  += scm[j][k] / (rs[j] * rs[k]);
        loc_conf += fabsf(plin2(pwW[6], pwC[6], dist[j][k]) - 0.5f) * (1.f / (OBJ_*OBJ_));
    }
    if (t < OBJ_) {
        float a = att_top[t];
        loc_tot  += plin2(pwW[0], pwC[0], a*a) / rs[t];
        loc_conf += fabsf(plin2(pwW[5], pwC[5], a) - 0.5f) * (1.f / OBJ_);
    }
    loc_tot  = blockReduceSum(loc_tot, red, 128);
    loc_conf = blockReduceSum(loc_conf, red, 128);

    if (t == 0) {
        float total = sqrtf(loc_tot + 1e-20f);
        float conf = plin2(pwW[7], pwC[7], loc_conf);
        confp[n] = conf;
        float s = fminf(fmaxf(total, 0.f), (float)OBJ_);
        float fl = floorf(s);
        int i = (int)fl; if (i > OBJ_) i = OBJ_; if (i < 0) i = 0;
        bc[0] = conf; bc[1] = s - fl; bc[2] = __int_as_float(i);
    }
    __syncthreads();
    if (t <= OBJ_) {
        float conf = bc[0], f = bc[1];
        int i = __float_as_int(bc[2]);
        int i1 = i + 1; if (i1 > OBJ_) i1 = OBJ_;
        float v = 0.f;
        if (t == i)  v += 1.f - f;
        if (t == i1) v += f;
        pred[(size_t)n * (OBJ_+1) + t] = conf * v;
    }
}

// ---------------- launch ----------------
extern "C" void kernel_launch(void* const* d_in, const int* in_sizes, int n_in,
                              void* d_out, int out_size) {
    const float* v_emb = (const float*)d_in[0];
    const float* q_emb = (const float*)d_in[1];
    const float* boxes = (const float*)d_in[2];
    const float* Wq    = (const float*)d_in[3];
    const float* bq    = (const float*)d_in[4];
    const float* Wk    = (const float*)d_in[5];
    const float* bk    = (const float*)d_in[6];
    const float* Wv    = (const float*)d_in[7];
    const float* bv    = (const float*)d_in[8];
    const float* in_w  = (const float*)d_in[9];
    const float* in_b  = (const float*)d_in[10];
    const float* out_w = (const float*)d_in[11];
    const float* out_b = (const float*)d_in[12];
    const float* ln_g  = (const float*)d_in[13];
    const float* ln_b  = (const float*)d_in[14];
    const float* l0_w  = (const float*)d_in[15];
    const float* l0_b  = (const float*)d_in[16];
    const float* l1_w  = (const float*)d_in[17];
    const float* l1_b  = (const float*)d_in[18];
    const float* lo_w  = (const float*)d_in[19];
    const float* lo_b  = (const float*)d_in[20];
    const float* pw    = (const float*)d_in[21];
    float* out = (float*)d_out;

    float *p_beff, *p_qkv, *p_inter, *p_x0, *p_x1, *p_qpool;
    __half *p_vh, *p_attnh, *p_interh, *p_Wqkvh, *p_Woh, *p_Wx0h;
    cudaGetSymbolAddress((void**)&p_beff,   g_beff);
    cudaGetSymbolAddress((void**)&p_qkv,    g_qkv);
    cudaGetSymbolAddress((void**)&p_inter,  g_inter);
    cudaGetSymbolAddress((void**)&p_x0,     g_x0);
    cudaGetSymbolAddress((void**)&p_x1,     g_x1);
    cudaGetSymbolAddress((void**)&p_qpool,  g_qpool);
    cudaGetSymbolAddress((void**)&p_vh,     g_vh);
    cudaGetSymbolAddress((void**)&p_attnh,  g_attnh);
    cudaGetSymbolAddress((void**)&p_interh, g_interh);
    cudaGetSymbolAddress((void**)&p_Wqkvh,  g_Wqkvh);
    cudaGetSymbolAddress((void**)&p_Woh,    g_Woh);
    cudaGetSymbolAddress((void**)&p_Wx0h,   g_Wx0h);

    cudaFuncSetAttribute(gemm_mma, cudaFuncAttributeMaxDynamicSharedMemorySize, GSMEM);

    // 1: split v_emb
    asplit_kernel<<<NR_, 128>>>(v_emb, p_vh);
    // 2: fuse projection weights, write fp16 split directly
    fusew_kernel<<<dim3(16, 16, 3), dim3(16, 16)>>>(in_w, Wq, Wk, Wv, p_Wqkvh);
    // 3: fuse bias
    fuseb_kernel<<<3, 256>>>(in_w, in_b, bq, bk, bv, p_beff);
    // 4: QKV projection (HMMA)  <-- ncu captures launch #4
    gemm_mma<<<dim3(6, NR_/128), 128, GSMEM>>>(p_vh, p_Wqkvh, p_beff, p_qkv, 3*D_);
    // 5: attention
    attn_kernel<<<N_*H_, 64>>>(p_qkv, p_attnh);
    // 6: split out-proj weights
    wsplit_kernel<<<D_, 128>>>(out_w, p_Woh, D_);
    // 7: output projection
    gemm_mma<<<dim3(2, NR_/128), 128, GSMEM>>>(p_attnh, p_Woh, out_b, p_inter, D_);
    // 8: layernorm -> fp16 3-term split
    ln_kernel<<<NR_, 256>>>(p_inter, ln_g, ln_b, p_interh);
    // 9: split x0 weights
    wsplit_kernel<<<768, 128>>>(l0_w, p_Wx0h, MM_);
    // 10: x0 GEMM
    gemm_mma<<<dim3(5, NR_/128), 128, GSMEM>>>(p_interh, p_Wx0h, l0_b, p_x0, MM_);
    // 11-12: question pooling + x1
    qpool_kernel<<<N_, 256>>>(q_emb, p_qpool);
    sgemm_bt<<<dim3((MM_+127)/128, N_/128), 256>>>(p_qpool, l1_w, l1_b, p_x1, N_, MM_, D_);
    // 13: MLB finalize -> scores
    mlb_kernel<<<NR_, 128>>>(p_x0, p_x1, lo_w, lo_b, out);
    // 14: counter
    counter_kernel<<<N_, 128>>>(out, boxes, pw, out + NR_, out + NR_ + (size_t)N_*(OBJ_+1));
}

// round 15
// speedup vs baseline: 1.1726x; 1.1726x over previous
#include <cuda_runtime.h>
#include <cuda_fp16.h>
#include <math.h>
#include <stdint.h>

#define N_   1024
#define R_   100
#define D_   256
#define T_   14
#define H_   8
#define MM_  600
#define OBJ_ 36
#define PLN_ 16
#define DH_  32
#define NR_  (N_*R_)   /* 102400 */
#define KP2  512       /* stored split cols: [hi|lo]; compute K' = 768 via remap */

// ---------------- scratch (device globals; no runtime allocation) ----------------
__device__ float g_beff[3*D_];
__device__ float g_qkv[(size_t)NR_*3*D_];
__device__ float g_inter[(size_t)NR_*D_];
__device__ float g_x0[(size_t)NR_*MM_];
__device__ float g_x1[(size_t)N_*MM_];
__device__ float g_qpool[(size_t)N_*D_];
__device__ __half g_vh[(size_t)NR_*KP2];
__device__ __half g_attnh[(size_t)NR_*KP2];
__device__ __half g_interh[(size_t)NR_*KP2];
__device__ __half g_Wqkvh[(size_t)(3*D_)*KP2];
__device__ __half g_Woh[(size_t)D_*KP2];
__device__ __half g_Wx0h[(size_t)640*KP2];

// ---------------- helpers ----------------
__device__ __forceinline__ float blockReduceSum(float v, float* red, int nthr) {
    int t = threadIdx.x;
    red[t] = v; __syncthreads();
    for (int s = nthr >> 1; s > 0; s >>= 1) {
        if (t < s) red[t] += red[t + s];
        __syncthreads();
    }
    float r = red[0]; __syncthreads();
    return r;
}

__device__ __forceinline__ uint32_t smem_u32(const void* p) {
    return (uint32_t)__cvta_generic_to_shared(p);
}

__device__ __forceinline__ void split_f16(float x, __half& hi, __half& lo) {
    hi = __float2half_rn(x);
    lo = __float2half_rn(x - __half2float(hi));
}

__device__ __forceinline__ void ldsm4(uint32_t* r, uint32_t addr) {
    asm volatile("ldmatrix.sync.aligned.m8n8.x4.shared.b16 {%0,%1,%2,%3}, [%4];"
                 : "=r"(r[0]), "=r"(r[1]), "=r"(r[2]), "=r"(r[3]) : "r"(addr));
}

__device__ __forceinline__ void mma16816(float* d, const uint32_t* a,
                                         uint32_t b0, uint32_t b1) {
    asm volatile(
        "mma.sync.aligned.m16n8k16.row.col.f32.f16.f16.f32 "
        "{%0,%1,%2,%3}, {%4,%5,%6,%7}, {%8,%9}, {%0,%1,%2,%3};"
        : "+f"(d[0]), "+f"(d[1]), "+f"(d[2]), "+f"(d[3])
        : "r"(a[0]), "r"(a[1]), "r"(a[2]), "r"(a[3]), "r"(b0), "r"(b1));
}

// k-block (32 cols each) -> stored offset in halves.
// Compute order: kb 0-7 = a_hi*w_hi, kb 8-15 = a_hi*w_lo, kb 16-23 = a_lo*w_hi.
__device__ __forceinline__ int aoff(int kb) {
    return (((kb >> 3) == 2) ? 256 : 0) + (kb & 7) * 32;
}
__device__ __forceinline__ int boff(int kb) {
    return (((kb >> 3) == 1) ? 256 : 0) + (kb & 7) * 32;
}

// ---------------- weight fusion: Weff = in_w_part @ W_part -> fp16 [hi|lo] -------
__global__ void fusew_kernel(const float* __restrict__ in_w,
                             const float* __restrict__ Wq,
                             const float* __restrict__ Wk,
                             const float* __restrict__ Wv,
                             __half* __restrict__ Wh) {
    int p = blockIdx.z;
    const float* W = (p == 0) ? Wq : ((p == 1) ? Wk : Wv);
    __shared__ float Ai[16][16];
    __shared__ float Bi[16][17];
    int tx = threadIdx.x, ty = threadIdx.y;
    int o = blockIdx.y * 16 + ty;
    int k = blockIdx.x * 16 + tx;
    float acc = 0.f;
    for (int j0 = 0; j0 < D_; j0 += 16) {
        Ai[ty][tx] = in_w[(size_t)(p*D_ + o)*D_ + j0 + tx];
        Bi[ty][tx] = W[(size_t)(j0 + ty)*D_ + k];
        __syncthreads();
        #pragma unroll
        for (int jj = 0; jj < 16; jj++) acc += Ai[ty][jj] * Bi[jj][tx];
        __syncthreads();
    }
    __half hi, lo;
    split_f16(acc, hi, lo);
    __half* yr = Wh + (size_t)(p*D_ + o) * KP2;
    yr[k] = hi; yr[D_ + k] = lo;
}

__global__ void fuseb_kernel(const float* __restrict__ in_w,
                             const float* __restrict__ in_b,
                             const float* __restrict__ bq,
                             const float* __restrict__ bk,
                             const float* __restrict__ bv,
                             float* __restrict__ beff) {
    int o = blockIdx.x * blockDim.x + threadIdx.x;
    if (o >= 3*D_) return;
    int p = o / D_;
    const float* bb = (p == 0) ? bq : ((p == 1) ? bk : bv);
    const float* wrow = in_w + (size_t)o * D_;
    float s = in_b[o];
    for (int j = 0; j < D_; j++) s += wrow[j] * bb[j];
    beff[o] = s;
}

// ---------------- activation split: [hi|lo] ----------------
__global__ __launch_bounds__(128) void asplit_kernel(const float* __restrict__ X,
                                                     __half* __restrict__ Y) {
    size_t row = blockIdx.x;
    int k = threadIdx.x * 2;
    float2 v = *(const float2*)(X + row * D_ + k);
    __half h0, l0, h1, l1;
    split_f16(v.x, h0, l0);
    split_f16(v.y, h1, l1);
    __half2 hp; hp.x = h0; hp.y = h1;
    __half2 lp; lp.x = l0; lp.y = l1;
    __half2* yr = (__half2*)(Y + row * KP2);
    int o = k >> 1;
    yr[o] = hp;
    yr[(D_ >> 1) + o] = lp;
}

// ---------------- weight split: [hi|lo] ----------------
__global__ __launch_bounds__(128) void wsplit_kernel(const float* __restrict__ W,
                                                     __half* __restrict__ Y, int Nc) {
    int r = blockIdx.x;
    int k = threadIdx.x * 2;
    float2 v = make_float2(0.f, 0.f);
    if (r < Nc) v = *(const float2*)(W + (size_t)r * D_ + k);
    __half h0, l0, h1, l1;
    split_f16(v.x, h0, l0);
    split_f16(v.y, h1, l1);
    __half2 hp; hp.x = h0; hp.y = h1;
    __half2 lp; lp.x = l0; lp.y = l1;
    __half2* yr = (__half2*)(Y + (size_t)r * KP2);
    int o = k >> 1;
    yr[o] = hp;
    yr[(D_ >> 1) + o] = lp;
}

// ---------------- HMMA GEMM: C[M,Nc] f32 = split-A * split-B^T + bias ------------
// 128x128 tile, BK=32, 256 threads (8 warps as 2m x 4n, 64x32 per warp),
// register-staged double buffer, 24 logical k-blocks over stored 512 cols.
#define SROW 40   /* padded row stride in halves (80 B) */

__global__ __launch_bounds__(256, 2) void gemm_mma(const __half* __restrict__ A,
                                                   const __half* __restrict__ B,
                                                   const float* __restrict__ bias,
                                                   float* __restrict__ C, int Nc) {
    __shared__ __half sA[2][128*SROW];
    __shared__ __half sB[2][128*SROW];
    int tid = threadIdx.x;
    int wid = tid >> 5, lane = tid & 31;
    int wm = wid & 1, wn = wid >> 1;
    int m0 = blockIdx.y * 128, n0 = blockIdx.x * 128;

    int lrow = tid >> 1;            // 0..127
    int lpart = (tid & 1) * 16;     // halves offset within 32-col row
    const __half* Agb = A + (size_t)(m0 + lrow) * KP2 + lpart;
    const __half* Bgb = B + (size_t)(n0 + lrow) * KP2 + lpart;

    float acc[4][4][4];
    #pragma unroll
    for (int i = 0; i < 4; i++)
        #pragma unroll
        for (int j = 0; j < 4; j++)
            #pragma unroll
            for (int q = 0; q < 4; q++) acc[i][j][q] = 0.f;

    uint4 ra0, ra1, rb0, rb1;
    // prologue: kb 0 (aoff=0, boff=0) -> buffer 0
    ra0 = *(const uint4*)(Agb);
    ra1 = *(const uint4*)(Agb + 8);
    rb0 = *(const uint4*)(Bgb);
    rb1 = *(const uint4*)(Bgb + 8);
    *(uint4*)&sA[0][lrow*SROW + lpart]     = ra0;
    *(uint4*)&sA[0][lrow*SROW + lpart + 8] = ra1;
    *(uint4*)&sB[0][lrow*SROW + lpart]     = rb0;
    *(uint4*)&sB[0][lrow*SROW + lpart + 8] = rb1;
    __syncthreads();

    int arow = wm*64 + (lane & 15);
    int brow = wn*32 + (lane & 15);
    int colb = (lane >> 4) * 8;

    for (int kb = 0; kb < 24; kb++) {
        bool hn = (kb < 23);
        if (hn) {
            const __half* An = Agb + aoff(kb + 1);
            const __half* Bn = Bgb + boff(kb + 1);
            ra0 = *(const uint4*)(An);
            ra1 = *(const uint4*)(An + 8);
            rb0 = *(const uint4*)(Bn);
            rb1 = *(const uint4*)(Bn + 8);
        }
        int bf = kb & 1;
        #pragma unroll
        for (int ks = 0; ks < 2; ks++) {
            uint32_t af[4][4], bfr[2][4];
            #pragma unroll
            for (int mi = 0; mi < 4; mi++)
                ldsm4(af[mi], smem_u32(&sA[bf][(arow + mi*16)*SROW + ks*16 + colb]));
            #pragma unroll
            for (int ni = 0; ni < 2; ni++)
                ldsm4(bfr[ni], smem_u32(&sB[bf][(brow + ni*16)*SROW + ks*16 + colb]));
            #pragma unroll
            for (int mi = 0; mi < 4; mi++) {
                #pragma unroll
                for (int ni = 0; ni < 2; ni++) {
                    mma16816(acc[mi][2*ni],   af[mi], bfr[ni][0], bfr[ni][2]);
                    mma16816(acc[mi][2*ni+1], af[mi], bfr[ni][1], bfr[ni][3]);
                }
            }
        }
        if (hn) {
            int nb = bf ^ 1;
            *(uint4*)&sA[nb][lrow*SROW + lpart]     = ra0;
            *(uint4*)&sA[nb][lrow*SROW + lpart + 8] = ra1;
            *(uint4*)&sB[nb][lrow*SROW + lpart]     = rb0;
            *(uint4*)&sB[nb][lrow*SROW + lpart + 8] = rb1;
            __syncthreads();
        }
    }

    // epilogue
    int rbase = m0 + wm*64 + (lane >> 2);
    int cbase = n0 + wn*32 + (lane & 3)*2;
    #pragma unroll
    for (int mi = 0; mi < 4; mi++) {
        #pragma unroll
        for (int nj = 0; nj < 4; nj++) {
            int r = rbase + mi*16;
            int c = cbase + nj*8;
            if (c < Nc) {
                float b0v = bias[c];
                C[(size_t)r * Nc + c]       = acc[mi][nj][0] + b0v;
                C[(size_t)(r+8) * Nc + c]   = acc[mi][nj][2] + b0v;
            }
            if (c + 1 < Nc) {
                float b1v = bias[c+1];
                C[(size_t)r * Nc + c + 1]     = acc[mi][nj][1] + b1v;
                C[(size_t)(r+8) * Nc + c + 1] = acc[mi][nj][3] + b1v;
            }
        }
    }
}

// ---------------- SIMT SGEMM (tiny x1) ----------------
__global__ __launch_bounds__(256) void sgemm_bt(const float* __restrict__ A,
                                                const float* __restrict__ B,
                                                const float* __restrict__ bias,
                                                float* __restrict__ C,
                                                int M, int Nc, int K) {
    __shared__ float As[2][16][128];
    __shared__ float Bs[2][16][128];
    int tid = threadIdx.x;
    int tcol = tid & 15, trow = tid >> 4;
    int lRow = tid >> 1;
    int lCol = (tid & 1) * 8;
    const float* Ab = A + ((size_t)blockIdx.y * 128 + lRow) * K + lCol;
    int bRowG = blockIdx.x * 128 + lRow;
    const float* Bb = B + (size_t)bRowG * K + lCol;
    bool bvalid = (bRowG < Nc);

    float acc[8][8];
    #pragma unroll
    for (int i = 0; i < 8; i++)
        #pragma unroll
        for (int j = 0; j < 8; j++) acc[i][j] = 0.f;

    float4 a0, a1, b0, b1;
    const float4 z4 = make_float4(0.f, 0.f, 0.f, 0.f);
    a0 = *(const float4*)(Ab);
    a1 = *(const float4*)(Ab + 4);
    b0 = bvalid ? *(const float4*)(Bb)     : z4;
    b1 = bvalid ? *(const float4*)(Bb + 4) : z4;
    As[0][lCol+0][lRow] = a0.x; As[0][lCol+1][lRow] = a0.y;
    As[0][lCol+2][lRow] = a0.z; As[0][lCol+3][lRow] = a0.w;
    As[0][lCol+4][lRow] = a1.x; As[0][lCol+5][lRow] = a1.y;
    As[0][lCol+6][lRow] = a1.z; As[0][lCol+7][lRow] = a1.w;
    Bs[0][lCol+0][lRow] = b0.x; Bs[0][lCol+1][lRow] = b0.y;
    Bs[0][lCol+2][lRow] = b0.z; Bs[0][lCol+3][lRow] = b0.w;
    Bs[0][lCol+4][lRow] = b1.x; Bs[0][lCol+5][lRow] = b1.y;
    Bs[0][lCol+6][lRow] = b1.z; Bs[0][lCol+7][lRow] = b1.w;
    __syncthreads();

    int buf = 0;
    for (int k0 = 0; k0 < K; k0 += 16) {
        bool hn = (k0 + 16 < K);
        if (hn) {
            a0 = *(const float4*)(Ab + k0 + 16);
            a1 = *(const float4*)(Ab + k0 + 20);
            b0 = bvalid ? *(const float4*)(Bb + k0 + 16) : z4;
            b1 = bvalid ? *(const float4*)(Bb + k0 + 20) : z4;
        }
        #pragma unroll
        for (int kk = 0; kk < 16; kk++) {
            float ar[8], br[8];
            *(float4*)(ar)     = *(const float4*)&As[buf][kk][trow*8];
            *(float4*)(ar + 4) = *(const float4*)&As[buf][kk][trow*8 + 4];
            *(float4*)(br)     = *(const float4*)&Bs[buf][kk][tcol*8];
            *(float4*)(br + 4) = *(const float4*)&Bs[buf][kk][tcol*8 + 4];
            #pragma unroll
            for (int i = 0; i < 8; i++)
                #pragma unroll
                for (int j = 0; j < 8; j++) acc[i][j] += ar[i] * br[j];
        }
        if (hn) {
            int nb = buf ^ 1;
            As[nb][lCol+0][lRow] = a0.x; As[nb][lCol+1][lRow] = a0.y;
            As[nb][lCol+2][lRow] = a0.z; As[nb][lCol+3][lRow] = a0.w;
            As[nb][lCol+4][lRow] = a1.x; As[nb][lCol+5][lRow] = a1.y;
            As[nb][lCol+6][lRow] = a1.z; As[nb][lCol+7][lRow] = a1.w;
            Bs[nb][lCol+0][lRow] = b0.x; Bs[nb][lCol+1][lRow] = b0.y;
            Bs[nb][lCol+2][lRow] = b0.z; Bs[nb][lCol+3][lRow] = b0.w;
            Bs[nb][lCol+4][lRow] = b1.x; Bs[nb][lCol+5][lRow] = b1.y;
            Bs[nb][lCol+6][lRow] = b1.z; Bs[nb][lCol+7][lRow] = b1.w;
            __syncthreads();
            buf = nb;
        }
    }

    int rb = blockIdx.y * 128 + trow * 8;
    int cb = blockIdx.x * 128 + tcol * 8;
    for (int i = 0; i < 8; i++) {
        size_t ro = (size_t)(rb + i) * Nc;
        #pragma unroll
        for (int j = 0; j < 8; j++) {
            int c = cb + j;
            if (c < Nc) C[ro + c] = acc[i][j] + bias[c];
        }
    }
}

// ---------------- attention: per (n,h); writes fp16 [hi|lo] split ----------------
__global__ __launch_bounds__(64) void attn_kernel(const float* __restrict__ qkv,
                                                  __half* __restrict__ outh) {
    __shared__ float Ks[R_][DH_];
    __shared__ float Vs[R_][DH_];
    int b = blockIdx.x;
    int n = b >> 3, h = b & 7;
    const float* base = qkv + (size_t)n * R_ * (3*D_) + h * DH_;
    for (int t = threadIdx.x; t < R_ * 8; t += 64) {
        int r = t >> 3, c = (t & 7) * 4;
        const float* p = base + (size_t)r * (3*D_) + c;
        *(float4*)&Ks[r][c] = *(const float4*)(p + D_);
        *(float4*)&Vs[r][c] = *(const float4*)(p + 2*D_);
    }
    __syncthreads();

    int t = threadIdx.x;
    if (t < 50) {
        const float scale = 0.17677669529663687f;  // 1/sqrt(32)
        int r0 = t, r1 = t + 50;
        float q0[DH_], q1[DH_];
        const float* p0 = base + (size_t)r0 * (3*D_);
        const float* p1 = base + (size_t)r1 * (3*D_);
        #pragma unroll
        for (int d = 0; d < DH_; d += 4) {
            float4 v0 = *(const float4*)(p0 + d);
            float4 v1 = *(const float4*)(p1 + d);
            q0[d+0] = v0.x * scale; q0[d+1] = v0.y * scale;
            q0[d+2] = v0.z * scale; q0[d+3] = v0.w * scale;
            q1[d+0] = v1.x * scale; q1[d+1] = v1.y * scale;
            q1[d+2] = v1.z * scale; q1[d+3] = v1.w * scale;
        }
        float acc0[DH_], acc1[DH_];
        #pragma unroll
        for (int d = 0; d < DH_; d++) { acc0[d] = 0.f; acc1[d] = 0.f; }
        float s0 = 0.f, s1 = 0.f;
        for (int k = 0; k < R_; k++) {
            float d0 = 0.f, d1 = 0.f;
            #pragma unroll
            for (int d = 0; d < DH_; d++) {
                float kv = Ks[k][d];
                d0 += q0[d] * kv;
                d1 += q1[d] * kv;
            }
            float w0 = __expf(d0), w1 = __expf(d1);
            s0 += w0; s1 += w1;
            #pragma unroll
            for (int d = 0; d < DH_; d++) {
                float vv = Vs[k][d];
                acc0[d] += w0 * vv;
                acc1[d] += w1 * vv;
            }
        }
        float i0 = 1.f / s0, i1 = 1.f / s1;
        __half2* ob0 = (__half2*)(outh + (size_t)(n * R_ + r0) * KP2 + h * DH_);
        __half2* ob1 = (__half2*)(outh + (size_t)(n * R_ + r1) * KP2 + h * DH_);
        #pragma unroll
        for (int d = 0; d < DH_; d += 2) {
            float xa = acc0[d] * i0, xb = acc0[d+1] * i0;
            float ya = acc1[d] * i1, yb = acc1[d+1] * i1;
            __half ha0, la0, hb0, lb0, ha1, la1, hb1, lb1;
            split_f16(xa, ha0, la0); split_f16(xb, hb0, lb0);
            split_f16(ya, ha1, la1); split_f16(yb, hb1, lb1);
            __half2 h2a; h2a.x = ha0; h2a.y = hb0;
            __half2 l2a; l2a.x = la0; l2a.y = lb0;
            __half2 h2b; h2b.x = ha1; h2b.y = hb1;
            __half2 l2b; l2b.x = la1; l2b.y = lb1;
            int o = d >> 1;
            ob0[o] = h2a; ob0[(D_ >> 1) + o] = l2a;
            ob1[o] = h2b; ob1[(D_ >> 1) + o] = l2b;
        }
    }
}

// ---------------- layernorm: fp32 in, fp16 [hi|lo] out ----------------
__global__ __launch_bounds__(256) void ln_kernel(const float* __restrict__ X,
                                                 const float* __restrict__ g,
                                                 const float* __restrict__ b,
                                                 __half* __restrict__ Yh) {
    __shared__ float red[256];
    int row = blockIdx.x, t = threadIdx.x;
    float v = X[(size_t)row * D_ + t];
    float mu = blockReduceSum(v, red, 256) * (1.f / D_);
    float d = v - mu;
    float var = blockReduceSum(d * d, red, 256) * (1.f / D_);
    float y = d * rsqrtf(var + 1e-5f) * g[t] + b[t];
    __half hi, lo;
    split_f16(y, hi, lo);
    __half* yr = Yh + (size_t)row * KP2;
    yr[t] = hi; yr[D_ + t] = lo;
}

// ---------------- question pool ----------------
__global__ void qpool_kernel(const float* __restrict__ q_emb, float* __restrict__ qp) {
    int n = blockIdx.x, d = threadIdx.x;
    float s = 0.f;
    for (int tt = 0; tt < T_; tt++) s += q_emb[((size_t)n * T_ + tt) * D_ + d];
    qp[(size_t)n * D_ + d] = s * (1.f / T_);
}

// ---------------- MLB finalize ----------------
__global__ __launch_bounds__(128) void mlb_kernel(const float* __restrict__ x0,
                                                  const float* __restrict__ x1,
                                                  const float* __restrict__ lo_w,
                                                  const float* __restrict__ lo_b,
                                                  float* __restrict__ scores) {
    __shared__ float red[128];
    int nr = blockIdx.x;
    int n = nr / R_;
    const float* a = x0 + (size_t)nr * MM_;
    const float* bv = x1 + (size_t)n * MM_;
    float s_abs = 0.f, s_dot = 0.f;
    for (int j = threadIdx.x; j < MM_; j += 128) {
        float z = a[j] * bv[j];
        float az = fabsf(z);
        float ss = copysignf(sqrtf(az), z);
        s_abs += az;
        s_dot += ss * lo_w[j];
    }
    s_abs = blockReduceSum(s_abs, red, 128);
    s_dot = blockReduceSum(s_dot, red, 128);
    if (threadIdx.x == 0) {
        float nrm = fmaxf(sqrtf(s_abs), 1e-12f);
        float val = s_dot / nrm + lo_b[0];
        scores[nr] = 1.f / (1.f + __expf(-val));
    }
}

// ---------------- counter ----------------
__device__ __forceinline__ float plin2(const float* __restrict__ w,
                                       const float* __restrict__ c, float x) {
    float y = 16.f * __saturatef(x);
    float fl = floorf(y);
    int i = (int)fl; if (i > 16) i = 16; if (i < 0) i = 0;
    float fr = y - fl;
    int i1 = i + 1; if (i1 > 16) i1 = 16;
    return c[i] + fr * w[i1];
}

__global__ __launch_bounds__(128) void counter_kernel(const float* __restrict__ scores,
                                                      const float* __restrict__ boxes,
                                                      const float* __restrict__ pw,
                                                      float* __restrict__ pred,
                                                      float* __restrict__ confp) {
    __shared__ float satt[R_];
    __shared__ float rv[128];
    __shared__ int   ri[128];
    __shared__ float pwW[8][PLN_+1], pwC[8][PLN_+1];
    __shared__ float att_top[OBJ_], bx[OBJ_][4], area[OBJ_];
    __shared__ float dist[OBJ_][OBJ_], dsc[OBJ_][OBJ_], scm[OBJ_][OBJ_], simm[OBJ_][OBJ_];
    __shared__ float rs[OBJ_];
    __shared__ float red[128];
    __shared__ float bc[3];

    int n = blockIdx.x, t = threadIdx.x;
    if (t < R_) satt[t] = scores[(size_t)n * R_ + t];
    if (t < 8) {
        float tmp[PLN_+1]; float sum = 0.f;
        for (int j = 0; j <= PLN_; j++) {
            float a = fabsf(pw[t*(PLN_+1) + j]);
            if (j == 0) a = 0.f;
            tmp[j] = a; sum += a;
        }
        float inv = 1.f / sum, c = 0.f;
        for (int j = 0; j <= PLN_; j++) {
            float wj = tmp[j] * inv;
            pwW[t][j] = wj; c += wj; pwC[t][j] = c;
        }
    }
    __syncthreads();

    for (int it = 0; it < OBJ_; it++) {
        float bvv = -1e30f; int bii = -1;
        if (t < R_) { bvv = satt[t]; bii = t; }
        rv[t] = bvv; ri[t] = bii; __syncthreads();
        for (int s = 64; s > 0; s >>= 1) {
            if (t < s) {
                float ov = rv[t+s]; int oi = ri[t+s];
                if (ov > rv[t] || (ov == rv[t] && oi >= 0 && (ri[t] < 0 || oi < ri[t]))) {
                    rv[t] = ov; ri[t] = oi;
                }
            }
            __syncthreads();
        }
        if (t == 0) {
            int id = ri[0];
            att_top[it] = rv[0];
            satt[id] = -1e30f;
            const float* bp = boxes + ((size_t)n * R_ + id) * 4;
            bx[it][0] = bp[0]; bx[it][1] = bp[1]; bx[it][2] = bp[2]; bx[it][3] = bp[3];
        }
        __syncthreads();
    }

    if (t < OBJ_)
        area[t] = fmaxf(bx[t][2]-bx[t][0], 0.f) * fmaxf(bx[t][3]-bx[t][1], 0.f);
    __syncthreads();

    for (int u = t; u < OBJ_*OBJ_; u += 128) {
        int j = u / OBJ_, k = u % OBJ_;
        float xx1 = fmaxf(bx[j][0], bx[k][0]), yy1 = fmaxf(bx[j][1], bx[k][1]);
        float xx2 = fminf(bx[j][2], bx[k][2]), yy2 = fminf(bx[j][3], bx[k][3]);
        float iw = fmaxf(xx2-xx1, 0.f), ih = fmaxf(yy2-yy1, 0.f);
        float inter = iw * ih;
        float iou = inter / (area[j] + area[k] - inter + 1e-12f);
        float dd = 1.f - iou;
        dist[j][k] = dd;
        float rel = att_top[j] * att_top[k];
        scm[j][k] = plin2(pwW[0], pwC[0], rel) * plin2(pwW[1], pwC[1], dd);
        dsc[j][k] = plin2(pwW[3], pwC[3], rel) * plin2(pwW[4], pwC[4], dd);
    }
    __syncthreads();

    for (int u = t; u < OBJ_*OBJ_; u += 128) {
        int j = u / OBJ_, k = u % OBJ_;
        float p = plin2(pwW[2], pwC[2], 1.f - fabsf(att_top[j] - att_top[k]));
        #pragma unroll 4
        for (int i = 0; i < OBJ_; i++)
            p *= plin2(pwW[2], pwC[2], 1.f - fabsf(dsc[i][j] - dsc[i][k]));
        simm[j][k] = p;
    }
    __syncthreads();

    if (t < OBJ_) {
        float s = 0.f;
        for (int k = 0; k < OBJ_; k++) s += simm[t][k];
        rs[t] = s;
    }
    __syncthreads();

    float loc_tot = 0.f, loc_conf = 0.f;
    for (int u = t; u < OBJ_*OBJ_; u += 128) {
        int j = u / OBJ_, k = u % OBJ_;
        loc_tot  += scm[j][k] / (rs[j] * rs[k]);
        loc_conf += fabsf(plin2(pwW[6], pwC[6], dist[j][k]) - 0.5f) * (1.f / (OBJ_*OBJ_));
    }
    if (t < OBJ_) {
        float a = att_top[t];
        loc_tot  += plin2(pwW[0], pwC[0], a*a) / rs[t];
        loc_conf += fabsf(plin2(pwW[5], pwC[5], a) - 0.5f) * (1.f / OBJ_);
    }
    loc_tot  = blockReduceSum(loc_tot, red, 128);
    loc_conf = blockReduceSum(loc_conf, red, 128);

    if (t == 0) {
        float total = sqrtf(loc_tot + 1e-20f);
        float conf = plin2(pwW[7], pwC[7], loc_conf);
        confp[n] = conf;
        float s = fminf(fmaxf(total, 0.f), (float)OBJ_);
        float fl = floorf(s);
        int i = (int)fl; if (i > OBJ_) i = OBJ_; if (i < 0) i = 0;
        bc[0] = conf; bc[1] = s - fl; bc[2] = __int_as_float(i);
    }
    __syncthreads();
    if (t <= OBJ_) {
        float conf = bc[0], f = bc[1];
        int i = __float_as_int(bc[2]);
        int i1 = i + 1; if (i1 > OBJ_) i1 = OBJ_;
        float v = 0.f;
        if (t == i)  v += 1.f - f;
        if (t == i1) v += f;
        pred[(size_t)n * (OBJ_+1) + t] = conf * v;
    }
}

// ---------------- launch ----------------
extern "C" void kernel_launch(void* const* d_in, const int* in_sizes, int n_in,
                              void* d_out, int out_size) {
    const float* v_emb = (const float*)d_in[0];
    const float* q_emb = (const float*)d_in[1];
    const float* boxes = (const float*)d_in[2];
    const float* Wq    = (const float*)d_in[3];
    const float* bq    = (const float*)d_in[4];
    const float* Wk    = (const float*)d_in[5];
    const float* bk    = (const float*)d_in[6];
    const float* Wv    = (const float*)d_in[7];
    const float* bv    = (const float*)d_in[8];
    const float* in_w  = (const float*)d_in[9];
    const float* in_b  = (const float*)d_in[10];
    const float* out_w = (const float*)d_in[11];
    const float* out_b = (const float*)d_in[12];
    const float* ln_g  = (const float*)d_in[13];
    const float* ln_b  = (const float*)d_in[14];
    const float* l0_w  = (const float*)d_in[15];
    const float* l0_b  = (const float*)d_in[16];
    const float* l1_w  = (const float*)d_in[17];
    const float* l1_b  = (const float*)d_in[18];
    const float* lo_w  = (const float*)d_in[19];
    const float* lo_b  = (const float*)d_in[20];
    const float* pw    = (const float*)d_in[21];
    float* out = (float*)d_out;

    float *p_beff, *p_qkv, *p_inter, *p_x0, *p_x1, *p_qpool;
    __half *p_vh, *p_attnh, *p_interh, *p_Wqkvh, *p_Woh, *p_Wx0h;
    cudaGetSymbolAddress((void**)&p_beff,   g_beff);
    cudaGetSymbolAddress((void**)&p_qkv,    g_qkv);
    cudaGetSymbolAddress((void**)&p_inter,  g_inter);
    cudaGetSymbolAddress((void**)&p_x0,     g_x0);
    cudaGetSymbolAddress((void**)&p_x1,     g_x1);
    cudaGetSymbolAddress((void**)&p_qpool,  g_qpool);
    cudaGetSymbolAddress((void**)&p_vh,     g_vh);
    cudaGetSymbolAddress((void**)&p_attnh,  g_attnh);
    cudaGetSymbolAddress((void**)&p_interh, g_interh);
    cudaGetSymbolAddress((void**)&p_Wqkvh,  g_Wqkvh);
    cudaGetSymbolAddress((void**)&p_Woh,    g_Woh);
    cudaGetSymbolAddress((void**)&p_Wx0h,   g_Wx0h);

    // 1: split v_emb -> [hi|lo]
    asplit_kernel<<<NR_, 128>>>(v_emb, p_vh);
    // 2: fuse projection weights -> fp16 [hi|lo]
    fusew_kernel<<<dim3(16, 16, 3), dim3(16, 16)>>>(in_w, Wq, Wk, Wv, p_Wqkvh);
    // 3: fuse bias
    fuseb_kernel<<<3, 256>>>(in_w, in_b, bq, bk, bv, p_beff);
    // 4: QKV projection (HMMA)  <-- ncu captures launch #4
    gemm_mma<<<dim3(6, NR_/128), 256>>>(p_vh, p_Wqkvh, p_beff, p_qkv, 3*D_);
    // 5: attention
    attn_kernel<<<N_*H_, 64>>>(p_qkv, p_attnh);
    // 6: split out-proj weights
    wsplit_kernel<<<D_, 128>>>(out_w, p_Woh, D_);
    // 7: output projection
    gemm_mma<<<dim3(2, NR_/128), 256>>>(p_attnh, p_Woh, out_b, p_inter, D_);
    // 8: layernorm -> fp16 [hi|lo]
    ln_kernel<<<NR_, 256>>>(p_inter, ln_g, ln_b, p_interh);
    // 9: split x0 weights (640 rows, zero-padded past 600)
    wsplit_kernel<<<640, 128>>>(l0_w, p_Wx0h, MM_);
    // 10: x0 GEMM
    gemm_mma<<<dim3(5, NR_/128), 256>>>(p_interh, p_Wx0h, l0_b, p_x0, MM_);
    // 11-12: question pooling + x1
    qpool_kernel<<<N_, 256>>>(q_emb, p_qpool);
    sgemm_bt<<<dim3((MM_+127)/128, N_/128), 256>>>(p_qpool, l1_w, l1_b, p_x1, N_, MM_, D_);
    // 13: MLB finalize -> scores
    mlb_kernel<<<NR_, 128>>>(p_x0, p_x1, lo_w, lo_b, out);
    // 14: counter
    counter_kernel<<<N_, 128>>>(out, boxes, pw, out + NR_, out + NR_ + (size_t)N_*(OBJ_+1));
}

// round 16
// speedup vs baseline: 1.2542x; 1.0697x over previous
#include <cuda_runtime.h>
#include <cuda_fp16.h>
#include <math.h>
#include <stdint.h>

#define N_   1024
#define R_   100
#define D_   256
#define T_   14
#define H_   8
#define MM_  600
#define OBJ_ 36
#define PLN_ 16
#define DH_  32
#define NR_  (N_*R_)   /* 102400 */
#define KP2  512       /* stored split cols: [hi|lo]; compute K' = 768 via remap */

// ---------------- scratch (device globals; no runtime allocation) ----------------
__device__ float g_beff[3*D_];
__device__ float g_qkv[(size_t)NR_*3*D_];
__device__ float g_inter[(size_t)NR_*D_];
__device__ float g_x0[(size_t)NR_*MM_];
__device__ float g_x1[(size_t)N_*MM_];
__device__ float g_qpool[(size_t)N_*D_];
__device__ __half g_vh[(size_t)NR_*KP2];
__device__ __half g_attnh[(size_t)NR_*KP2];
__device__ __half g_interh[(size_t)NR_*KP2];
__device__ __half g_Wqkvh[(size_t)(3*D_)*KP2];
__device__ __half g_Woh[(size_t)D_*KP2];
__device__ __half g_Wx0h[(size_t)640*KP2];

// ---------------- helpers ----------------
__device__ __forceinline__ float warpReduceSum(float v) {
    #pragma unroll
    for (int o = 16; o > 0; o >>= 1) v += __shfl_xor_sync(0xFFFFFFFFu, v, o);
    return v;
}

__device__ __forceinline__ uint32_t smem_u32(const void* p) {
    return (uint32_t)__cvta_generic_to_shared(p);
}

__device__ __forceinline__ void split_f16(float x, __half& hi, __half& lo) {
    hi = __float2half_rn(x);
    lo = __float2half_rn(x - __half2float(hi));
}

__device__ __forceinline__ void ldsm4(uint32_t* r, uint32_t addr) {
    asm volatile("ldmatrix.sync.aligned.m8n8.x4.shared.b16 {%0,%1,%2,%3}, [%4];"
                 : "=r"(r[0]), "=r"(r[1]), "=r"(r[2]), "=r"(r[3]) : "r"(addr));
}

__device__ __forceinline__ void mma16816(float* d, const uint32_t* a,
                                         uint32_t b0, uint32_t b1) {
    asm volatile(
        "mma.sync.aligned.m16n8k16.row.col.f32.f16.f16.f32 "
        "{%0,%1,%2,%3}, {%4,%5,%6,%7}, {%8,%9}, {%0,%1,%2,%3};"
        : "+f"(d[0]), "+f"(d[1]), "+f"(d[2]), "+f"(d[3])
        : "r"(a[0]), "r"(a[1]), "r"(a[2]), "r"(a[3]), "r"(b0), "r"(b1));
}

// k-block (32 cols each) -> stored offset in halves.
// Compute order: kb 0-7 = a_hi*w_hi, kb 8-15 = a_hi*w_lo, kb 16-23 = a_lo*w_hi.
__device__ __forceinline__ int aoff(int kb) {
    return (((kb >> 3) == 2) ? 256 : 0) + (kb & 7) * 32;
}
__device__ __forceinline__ int boff(int kb) {
    return (((kb >> 3) == 1) ? 256 : 0) + (kb & 7) * 32;
}

// ---------------- weight fusion: Weff = in_w_part @ W_part -> fp16 [hi|lo] -------
__global__ void fusew_kernel(const float* __restrict__ in_w,
                             const float* __restrict__ Wq,
                             const float* __restrict__ Wk,
                             const float* __restrict__ Wv,
                             __half* __restrict__ Wh) {
    int p = blockIdx.z;
    const float* W = (p == 0) ? Wq : ((p == 1) ? Wk : Wv);
    __shared__ float Ai[16][16];
    __shared__ float Bi[16][17];
    int tx = threadIdx.x, ty = threadIdx.y;
    int o = blockIdx.y * 16 + ty;
    int k = blockIdx.x * 16 + tx;
    float acc = 0.f;
    for (int j0 = 0; j0 < D_; j0 += 16) {
        Ai[ty][tx] = in_w[(size_t)(p*D_ + o)*D_ + j0 + tx];
        Bi[ty][tx] = W[(size_t)(j0 + ty)*D_ + k];
        __syncthreads();
        #pragma unroll
        for (int jj = 0; jj < 16; jj++) acc += Ai[ty][jj] * Bi[jj][tx];
        __syncthreads();
    }
    __half hi, lo;
    split_f16(acc, hi, lo);
    __half* yr = Wh + (size_t)(p*D_ + o) * KP2;
    yr[k] = hi; yr[D_ + k] = lo;
}

__global__ void fuseb_kernel(const float* __restrict__ in_w,
                             const float* __restrict__ in_b,
                             const float* __restrict__ bq,
                             const float* __restrict__ bk,
                             const float* __restrict__ bv,
                             float* __restrict__ beff) {
    int o = blockIdx.x * blockDim.x + threadIdx.x;
    if (o >= 3*D_) return;
    int p = o / D_;
    const float* bb = (p == 0) ? bq : ((p == 1) ? bk : bv);
    const float* wrow = in_w + (size_t)o * D_;
    float s = in_b[o];
    for (int j = 0; j < D_; j++) s += wrow[j] * bb[j];
    beff[o] = s;
}

// ---------------- activation split: [hi|lo] ----------------
__global__ __launch_bounds__(128) void asplit_kernel(const float* __restrict__ X,
                                                     __half* __restrict__ Y) {
    size_t row = blockIdx.x;
    int k = threadIdx.x * 2;
    float2 v = *(const float2*)(X + row * D_ + k);
    __half h0, l0, h1, l1;
    split_f16(v.x, h0, l0);
    split_f16(v.y, h1, l1);
    __half2 hp; hp.x = h0; hp.y = h1;
    __half2 lp; lp.x = l0; lp.y = l1;
    __half2* yr = (__half2*)(Y + row * KP2);
    int o = k >> 1;
    yr[o] = hp;
    yr[(D_ >> 1) + o] = lp;
}

// ---------------- weight split: [hi|lo] ----------------
__global__ __launch_bounds__(128) void wsplit_kernel(const float* __restrict__ W,
                                                     __half* __restrict__ Y, int Nc) {
    int r = blockIdx.x;
    int k = threadIdx.x * 2;
    float2 v = make_float2(0.f, 0.f);
    if (r < Nc) v = *(const float2*)(W + (size_t)r * D_ + k);
    __half h0, l0, h1, l1;
    split_f16(v.x, h0, l0);
    split_f16(v.y, h1, l1);
    __half2 hp; hp.x = h0; hp.y = h1;
    __half2 lp; lp.x = l0; lp.y = l1;
    __half2* yr = (__half2*)(Y + (size_t)r * KP2);
    int o = k >> 1;
    yr[o] = hp;
    yr[(D_ >> 1) + o] = lp;
}

// ---------------- HMMA GEMM: C[M,Nc] f32 = split-A * split-B^T + bias ------------
// 128x128 tile, BK=32, 256 threads (8 warps as 2m x 4n, 64x32 per warp),
// register-staged double buffer, 24 logical k-blocks over stored 512 cols.
#define SROW 40   /* padded row stride in halves (80 B) */

__global__ __launch_bounds__(256, 2) void gemm_mma(const __half* __restrict__ A,
                                                   const __half* __restrict__ B,
                                                   const float* __restrict__ bias,
                                                   float* __restrict__ C, int Nc) {
    __shared__ __half sA[2][128*SROW];
    __shared__ __half sB[2][128*SROW];
    int tid = threadIdx.x;
    int wid = tid >> 5, lane = tid & 31;
    int wm = wid & 1, wn = wid >> 1;
    int m0 = blockIdx.y * 128, n0 = blockIdx.x * 128;

    int lrow = tid >> 1;            // 0..127
    int lpart = (tid & 1) * 16;     // halves offset within 32-col row
    const __half* Agb = A + (size_t)(m0 + lrow) * KP2 + lpart;
    const __half* Bgb = B + (size_t)(n0 + lrow) * KP2 + lpart;

    float acc[4][4][4];
    #pragma unroll
    for (int i = 0; i < 4; i++)
        #pragma unroll
        for (int j = 0; j < 4; j++)
            #pragma unroll
            for (int q = 0; q < 4; q++) acc[i][j][q] = 0.f;

    uint4 ra0, ra1, rb0, rb1;
    // prologue: kb 0 (aoff=0, boff=0) -> buffer 0
    ra0 = *(const uint4*)(Agb);
    ra1 = *(const uint4*)(Agb + 8);
    rb0 = *(const uint4*)(Bgb);
    rb1 = *(const uint4*)(Bgb + 8);
    *(uint4*)&sA[0][lrow*SROW + lpart]     = ra0;
    *(uint4*)&sA[0][lrow*SROW + lpart + 8] = ra1;
    *(uint4*)&sB[0][lrow*SROW + lpart]     = rb0;
    *(uint4*)&sB[0][lrow*SROW + lpart + 8] = rb1;
    __syncthreads();

    int arow = wm*64 + (lane & 15);
    int brow = wn*32 + (lane & 15);
    int colb = (lane >> 4) * 8;

    for (int kb = 0; kb < 24; kb++) {
        bool hn = (kb < 23);
        if (hn) {
            const __half* An = Agb + aoff(kb + 1);
            const __half* Bn = Bgb + boff(kb + 1);
            ra0 = *(const uint4*)(An);
            ra1 = *(const uint4*)(An + 8);
            rb0 = *(const uint4*)(Bn);
            rb1 = *(const uint4*)(Bn + 8);
        }
        int bf = kb & 1;
        #pragma unroll
        for (int ks = 0; ks < 2; ks++) {
            uint32_t af[4][4], bfr[2][4];
            #pragma unroll
            for (int mi = 0; mi < 4; mi++)
                ldsm4(af[mi], smem_u32(&sA[bf][(arow + mi*16)*SROW + ks*16 + colb]));
            #pragma unroll
            for (int ni = 0; ni < 2; ni++)
                ldsm4(bfr[ni], smem_u32(&sB[bf][(brow + ni*16)*SROW + ks*16 + colb]));
            #pragma unroll
            for (int mi = 0; mi < 4; mi++) {
                #pragma unroll
                for (int ni = 0; ni < 2; ni++) {
                    mma16816(acc[mi][2*ni],   af[mi], bfr[ni][0], bfr[ni][2]);
                    mma16816(acc[mi][2*ni+1], af[mi], bfr[ni][1], bfr[ni][3]);
                }
            }
        }
        if (hn) {
            int nb = bf ^ 1;
            *(uint4*)&sA[nb][lrow*SROW + lpart]     = ra0;
            *(uint4*)&sA[nb][lrow*SROW + lpart + 8] = ra1;
            *(uint4*)&sB[nb][lrow*SROW + lpart]     = rb0;
            *(uint4*)&sB[nb][lrow*SROW + lpart + 8] = rb1;
            __syncthreads();
        }
    }

    // epilogue
    int rbase = m0 + wm*64 + (lane >> 2);
    int cbase = n0 + wn*32 + (lane & 3)*2;
    #pragma unroll
    for (int mi = 0; mi < 4; mi++) {
        #pragma unroll
        for (int nj = 0; nj < 4; nj++) {
            int r = rbase + mi*16;
            int c = cbase + nj*8;
            if (c < Nc) {
                float b0v = bias[c];
                C[(size_t)r * Nc + c]       = acc[mi][nj][0] + b0v;
                C[(size_t)(r+8) * Nc + c]   = acc[mi][nj][2] + b0v;
            }
            if (c + 1 < Nc) {
                float b1v = bias[c+1];
                C[(size_t)r * Nc + c + 1]     = acc[mi][nj][1] + b1v;
                C[(size_t)(r+8) * Nc + c + 1] = acc[mi][nj][3] + b1v;
            }
        }
    }
}

// ---------------- SIMT SGEMM (tiny x1) ----------------
__global__ __launch_bounds__(256) void sgemm_bt(const float* __restrict__ A,
                                                const float* __restrict__ B,
                                                const float* __restrict__ bias,
                                                float* __restrict__ C,
                                                int M, int Nc, int K) {
    __shared__ float As[2][16][128];
    __shared__ float Bs[2][16][128];
    int tid = threadIdx.x;
    int tcol = tid & 15, trow = tid >> 4;
    int lRow = tid >> 1;
    int lCol = (tid & 1) * 8;
    const float* Ab = A + ((size_t)blockIdx.y * 128 + lRow) * K + lCol;
    int bRowG = blockIdx.x * 128 + lRow;
    const float* Bb = B + (size_t)bRowG * K + lCol;
    bool bvalid = (bRowG < Nc);

    float acc[8][8];
    #pragma unroll
    for (int i = 0; i < 8; i++)
        #pragma unroll
        for (int j = 0; j < 8; j++) acc[i][j] = 0.f;

    float4 a0, a1, b0, b1;
    const float4 z4 = make_float4(0.f, 0.f, 0.f, 0.f);
    a0 = *(const float4*)(Ab);
    a1 = *(const float4*)(Ab + 4);
    b0 = bvalid ? *(const float4*)(Bb)     : z4;
    b1 = bvalid ? *(const float4*)(Bb + 4) : z4;
    As[0][lCol+0][lRow] = a0.x; As[0][lCol+1][lRow] = a0.y;
    As[0][lCol+2][lRow] = a0.z; As[0][lCol+3][lRow] = a0.w;
    As[0][lCol+4][lRow] = a1.x; As[0][lCol+5][lRow] = a1.y;
    As[0][lCol+6][lRow] = a1.z; As[0][lCol+7][lRow] = a1.w;
    Bs[0][lCol+0][lRow] = b0.x; Bs[0][lCol+1][lRow] = b0.y;
    Bs[0][lCol+2][lRow] = b0.z; Bs[0][lCol+3][lRow] = b0.w;
    Bs[0][lCol+4][lRow] = b1.x; Bs[0][lCol+5][lRow] = b1.y;
    Bs[0][lCol+6][lRow] = b1.z; Bs[0][lCol+7][lRow] = b1.w;
    __syncthreads();

    int buf = 0;
    for (int k0 = 0; k0 < K; k0 += 16) {
        bool hn = (k0 + 16 < K);
        if (hn) {
            a0 = *(const float4*)(Ab + k0 + 16);
            a1 = *(const float4*)(Ab + k0 + 20);
            b0 = bvalid ? *(const float4*)(Bb + k0 + 16) : z4;
            b1 = bvalid ? *(const float4*)(Bb + k0 + 20) : z4;
        }
        #pragma unroll
        for (int kk = 0; kk < 16; kk++) {
            float ar[8], br[8];
            *(float4*)(ar)     = *(const float4*)&As[buf][kk][trow*8];
            *(float4*)(ar + 4) = *(const float4*)&As[buf][kk][trow*8 + 4];
            *(float4*)(br)     = *(const float4*)&Bs[buf][kk][tcol*8];
            *(float4*)(br + 4) = *(const float4*)&Bs[buf][kk][tcol*8 + 4];
            #pragma unroll
            for (int i = 0; i < 8; i++)
                #pragma unroll
                for (int j = 0; j < 8; j++) acc[i][j] += ar[i] * br[j];
        }
        if (hn) {
            int nb = buf ^ 1;
            As[nb][lCol+0][lRow] = a0.x; As[nb][lCol+1][lRow] = a0.y;
            As[nb][lCol+2][lRow] = a0.z; As[nb][lCol+3][lRow] = a0.w;
            As[nb][lCol+4][lRow] = a1.x; As[nb][lCol+5][lRow] = a1.y;
            As[nb][lCol+6][lRow] = a1.z; As[nb][lCol+7][lRow] = a1.w;
            Bs[nb][lCol+0][lRow] = b0.x; Bs[nb][lCol+1][lRow] = b0.y;
            Bs[nb][lCol+2][lRow] = b0.z; Bs[nb][lCol+3][lRow] = b0.w;
            Bs[nb][lCol+4][lRow] = b1.x; Bs[nb][lCol+5][lRow] = b1.y;
            Bs[nb][lCol+6][lRow] = b1.z; Bs[nb][lCol+7][lRow] = b1.w;
            __syncthreads();
            buf = nb;
        }
    }

    int rb = blockIdx.y * 128 + trow * 8;
    int cb = blockIdx.x * 128 + tcol * 8;
    for (int i = 0; i < 8; i++) {
        size_t ro = (size_t)(rb + i) * Nc;
        #pragma unroll
        for (int j = 0; j < 8; j++) {
            int c = cb + j;
            if (c < Nc) C[ro + c] = acc[i][j] + bias[c];
        }
    }
}

// ---------------- attention: per (n,h); writes fp16 [hi|lo] split ----------------
__global__ __launch_bounds__(64) void attn_kernel(const float* __restrict__ qkv,
                                                  __half* __restrict__ outh) {
    __shared__ float Ks[R_][DH_];
    __shared__ float Vs[R_][DH_];
    int b = blockIdx.x;
    int n = b >> 3, h = b & 7;
    const float* base = qkv + (size_t)n * R_ * (3*D_) + h * DH_;
    for (int t = threadIdx.x; t < R_ * 8; t += 64) {
        int r = t >> 3, c = (t & 7) * 4;
        const float* p = base + (size_t)r * (3*D_) + c;
        *(float4*)&Ks[r][c] = *(const float4*)(p + D_);
        *(float4*)&Vs[r][c] = *(const float4*)(p + 2*D_);
    }
    __syncthreads();

    int t = threadIdx.x;
    if (t < 50) {
        const float scale = 0.17677669529663687f;  // 1/sqrt(32)
        int r0 = t, r1 = t + 50;
        float q0[DH_], q1[DH_];
        const float* p0 = base + (size_t)r0 * (3*D_);
        const float* p1 = base + (size_t)r1 * (3*D_);
        #pragma unroll
        for (int d = 0; d < DH_; d += 4) {
            float4 v0 = *(const float4*)(p0 + d);
            float4 v1 = *(const float4*)(p1 + d);
            q0[d+0] = v0.x * scale; q0[d+1] = v0.y * scale;
            q0[d+2] = v0.z * scale; q0[d+3] = v0.w * scale;
            q1[d+0] = v1.x * scale; q1[d+1] = v1.y * scale;
            q1[d+2] = v1.z * scale; q1[d+3] = v1.w * scale;
        }
        float acc0[DH_], acc1[DH_];
        #pragma unroll
        for (int d = 0; d < DH_; d++) { acc0[d] = 0.f; acc1[d] = 0.f; }
        float s0 = 0.f, s1 = 0.f;
        for (int k = 0; k < R_; k++) {
            float d0 = 0.f, d1 = 0.f;
            #pragma unroll
            for (int d = 0; d < DH_; d++) {
                float kv = Ks[k][d];
                d0 += q0[d] * kv;
                d1 += q1[d] * kv;
            }
            float w0 = __expf(d0), w1 = __expf(d1);
            s0 += w0; s1 += w1;
            #pragma unroll
            for (int d = 0; d < DH_; d++) {
                float vv = Vs[k][d];
                acc0[d] += w0 * vv;
                acc1[d] += w1 * vv;
            }
        }
        float i0 = 1.f / s0, i1 = 1.f / s1;
        __half2* ob0 = (__half2*)(outh + (size_t)(n * R_ + r0) * KP2 + h * DH_);
        __half2* ob1 = (__half2*)(outh + (size_t)(n * R_ + r1) * KP2 + h * DH_);
        #pragma unroll
        for (int d = 0; d < DH_; d += 2) {
            float xa = acc0[d] * i0, xb = acc0[d+1] * i0;
            float ya = acc1[d] * i1, yb = acc1[d+1] * i1;
            __half ha0, la0, hb0, lb0, ha1, la1, hb1, lb1;
            split_f16(xa, ha0, la0); split_f16(xb, hb0, lb0);
            split_f16(ya, ha1, la1); split_f16(yb, hb1, lb1);
            __half2 h2a; h2a.x = ha0; h2a.y = hb0;
            __half2 l2a; l2a.x = la0; l2a.y = lb0;
            __half2 h2b; h2b.x = ha1; h2b.y = hb1;
            __half2 l2b; l2b.x = la1; l2b.y = lb1;
            int o = d >> 1;
            ob0[o] = h2a; ob0[(D_ >> 1) + o] = l2a;
            ob1[o] = h2b; ob1[(D_ >> 1) + o] = l2b;
        }
    }
}

// ---------------- layernorm: fp32 in, fp16 [hi|lo] out (shuffle reductions) ------
__global__ __launch_bounds__(256) void ln_kernel(const float* __restrict__ X,
                                                 const float* __restrict__ g,
                                                 const float* __restrict__ b,
                                                 __half* __restrict__ Yh) {
    __shared__ float part[8];
    __shared__ float bcast;
    int row = blockIdx.x, t = threadIdx.x;
    int w = t >> 5, lane = t & 31;
    float v = X[(size_t)row * D_ + t];

    float s = warpReduceSum(v);
    if (lane == 0) part[w] = s;
    __syncthreads();
    if (t == 0) {
        float tot = 0.f;
        #pragma unroll
        for (int i = 0; i < 8; i++) tot += part[i];
        bcast = tot * (1.f / D_);
    }
    __syncthreads();
    float mu = bcast;
    float d = v - mu;

    float s2 = warpReduceSum(d * d);
    if (lane == 0) part[w] = s2;
    __syncthreads();
    if (t == 0) {
        float tot = 0.f;
        #pragma unroll
        for (int i = 0; i < 8; i++) tot += part[i];
        bcast = tot * (1.f / D_);
    }
    __syncthreads();
    float var = bcast;

    float y = d * rsqrtf(var + 1e-5f) * g[t] + b[t];
    __half hi, lo;
    split_f16(y, hi, lo);
    __half* yr = Yh + (size_t)row * KP2;
    yr[t] = hi; yr[D_ + t] = lo;
}

// ---------------- question pool ----------------
__global__ void qpool_kernel(const float* __restrict__ q_emb, float* __restrict__ qp) {
    int n = blockIdx.x, d = threadIdx.x;
    float s = 0.f;
    for (int tt = 0; tt < T_; tt++) s += q_emb[((size_t)n * T_ + tt) * D_ + d];
    qp[(size_t)n * D_ + d] = s * (1.f / T_);
}

// ---------------- MLB finalize: one warp per row ----------------
__global__ __launch_bounds__(128) void mlb_kernel(const float* __restrict__ x0,
                                                  const float* __restrict__ x1,
                                                  const float* __restrict__ lo_w,
                                                  const float* __restrict__ lo_b,
                                                  float* __restrict__ scores) {
    int w = threadIdx.x >> 5, lane = threadIdx.x & 31;
    int nr = blockIdx.x * 4 + w;
    int n = nr / R_;
    const float* a = x0 + (size_t)nr * MM_;
    const float* bv = x1 + (size_t)n * MM_;
    float s_abs = 0.f, s_dot = 0.f;
    for (int j = lane; j < MM_; j += 32) {
        float z = a[j] * bv[j];
        float az = fabsf(z);
        float ss = copysignf(sqrtf(az), z);
        s_abs += az;
        s_dot += ss * lo_w[j];
    }
    s_abs = warpReduceSum(s_abs);
    s_dot = warpReduceSum(s_dot);
    if (lane == 0) {
        float nrm = fmaxf(sqrtf(s_abs), 1e-12f);
        float val = s_dot / nrm + lo_b[0];
        scores[nr] = 1.f / (1.f + __expf(-val));
    }
}

// ---------------- counter ----------------
__device__ __forceinline__ float plin2(const float* __restrict__ w,
                                       const float* __restrict__ c, float x) {
    float y = 16.f * __saturatef(x);
    float fl = floorf(y);
    int i = (int)fl; if (i > 16) i = 16; if (i < 0) i = 0;
    float fr = y - fl;
    int i1 = i + 1; if (i1 > 16) i1 = 16;
    return c[i] + fr * w[i1];
}

__global__ __launch_bounds__(128) void counter_kernel(const float* __restrict__ scores,
                                                      const float* __restrict__ boxes,
                                                      const float* __restrict__ pw,
                                                      float* __restrict__ pred,
                                                      float* __restrict__ confp) {
    __shared__ float satt[R_];
    __shared__ int   selidx[OBJ_];
    __shared__ float pwW[8][PLN_+1], pwC[8][PLN_+1];
    __shared__ float att_top[OBJ_], bx[OBJ_][4], area[OBJ_];
    __shared__ float dist[OBJ_][OBJ_], dsc[OBJ_][OBJ_], scm[OBJ_][OBJ_], simm[OBJ_][OBJ_];
    __shared__ float rs[OBJ_];
    __shared__ float red[128];
    __shared__ float bc[3];

    int n = blockIdx.x, t = threadIdx.x;
    if (t < R_) satt[t] = scores[(size_t)n * R_ + t];
    if (t < 8) {
        float tmp[PLN_+1]; float sum = 0.f;
        for (int j = 0; j <= PLN_; j++) {
            float a = fabsf(pw[t*(PLN_+1) + j]);
            if (j == 0) a = 0.f;
            tmp[j] = a; sum += a;
        }
        float inv = 1.f / sum, c = 0.f;
        for (int j = 0; j <= PLN_; j++) {
            float wj = tmp[j] * inv;
            pwW[t][j] = wj; c += wj; pwC[t][j] = c;
        }
    }
    __syncthreads();

    // rank-based top-36: identical set and ordering (desc value, ties by index)
    if (t < R_) {
        float v = satt[t];
        int rank = 0;
        #pragma unroll 4
        for (int j = 0; j < R_; j++) {
            float u = satt[j];
            rank += (u > v) || (u == v && j < t);
        }
        if (rank < OBJ_) {
            att_top[rank] = v;
            selidx[rank] = t;
        }
    }
    __syncthreads();

    if (t < OBJ_) {
        const float* bp = boxes + ((size_t)n * R_ + selidx[t]) * 4;
        float x1v = bp[0], y1v = bp[1], x2v = bp[2], y2v = bp[3];
        bx[t][0] = x1v; bx[t][1] = y1v; bx[t][2] = x2v; bx[t][3] = y2v;
        area[t] = fmaxf(x2v - x1v, 0.f) * fmaxf(y2v - y1v, 0.f);
    }
    __syncthreads();

    for (int u = t; u < OBJ_*OBJ_; u += 128) {
        int j = u / OBJ_, k = u % OBJ_;
        float xx1 = fmaxf(bx[j][0], bx[k][0]), yy1 = fmaxf(bx[j][1], bx[k][1]);
        float xx2 = fminf(bx[j][2], bx[k][2]), yy2 = fminf(bx[j][3], bx[k][3]);
        float iw = fmaxf(xx2-xx1, 0.f), ih = fmaxf(yy2-yy1, 0.f);
        float inter = iw * ih;
        float iou = inter / (area[j] + area[k] - inter + 1e-12f);
        float dd = 1.f - iou;
        dist[j][k] = dd;
        float rel = att_top[j] * att_top[k];
        scm[j][k] = plin2(pwW[0], pwC[0], rel) * plin2(pwW[1], pwC[1], dd);
        dsc[j][k] = plin2(pwW[3], pwC[3], rel) * plin2(pwW[4], pwC[4], dd);
    }
    __syncthreads();

    for (int u = t; u < OBJ_*OBJ_; u += 128) {
        int j = u / OBJ_, k = u % OBJ_;
        float p = plin2(pwW[2], pwC[2], 1.f - fabsf(att_top[j] - att_top[k]));
        #pragma unroll 4
        for (int i = 0; i < OBJ_; i++)
            p *= plin2(pwW[2], pwC[2], 1.f - fabsf(dsc[i][j] - dsc[i][k]));
        simm[j][k] = p;
    }
    __syncthreads();

    if (t < OBJ_) {
        float s = 0.f;
        for (int k = 0; k < OBJ_; k++) s += simm[t][k];
        rs[t] = s;
    }
    __syncthreads();

    float loc_tot = 0.f, loc_conf = 0.f;
    for (int u = t; u < OBJ_*OBJ_; u += 128) {
        int j = u / OBJ_, k = u % OBJ_;
        loc_tot  += scm[j][k] / (rs[j] * rs[k]);
        loc_conf += fabsf(plin2(pwW[6], pwC[6], dist[j][k]) - 0.5f) * (1.f / (OBJ_*OBJ_));
    }
    if (t < OBJ_) {
        float a = att_top[t];
        loc_tot  += plin2(pwW[0], pwC[0], a*a) / rs[t];
        loc_conf += fabsf(plin2(pwW[5], pwC[5], a) - 0.5f) * (1.f / OBJ_);
    }
    // block reduction (128 threads)
    {
        int w = t >> 5, lane = t & 31;
        loc_tot  = warpReduceSum(loc_tot);
        loc_conf = warpReduceSum(loc_conf);
        if (lane == 0) { red[w] = loc_tot; red[4 + w] = loc_conf; }
        __syncthreads();
        if (t == 0) {
            loc_tot  = red[0] + red[1] + red[2] + red[3];
            loc_conf = red[4] + red[5] + red[6] + red[7];
            float total = sqrtf(loc_tot + 1e-20f);
            float conf = plin2(pwW[7], pwC[7], loc_conf);
            confp[n] = conf;
            float s = fminf(fmaxf(total, 0.f), (float)OBJ_);
            float fl = floorf(s);
            int i = (int)fl; if (i > OBJ_) i = OBJ_; if (i < 0) i = 0;
            bc[0] = conf; bc[1] = s - fl; bc[2] = __int_as_float(i);
        }
    }
    __syncthreads();
    if (t <= OBJ_) {
        float conf = bc[0], f = bc[1];
        int i = __float_as_int(bc[2]);
        int i1 = i + 1; if (i1 > OBJ_) i1 = OBJ_;
        float v = 0.f;
        if (t == i)  v += 1.f - f;
        if (t == i1) v += f;
        pred[(size_t)n * (OBJ_+1) + t] = conf * v;
    }
}

// ---------------- launch ----------------
extern "C" void kernel_launch(void* const* d_in, const int* in_sizes, int n_in,
                              void* d_out, int out_size) {
    const float* v_emb = (const float*)d_in[0];
    const float* q_emb = (const float*)d_in[1];
    const float* boxes = (const float*)d_in[2];
    const float* Wq    = (const float*)d_in[3];
    const float* bq    = (const float*)d_in[4];
    const float* Wk    = (const float*)d_in[5];
    const float* bk    = (const float*)d_in[6];
    const float* Wv    = (const float*)d_in[7];
    const float* bv    = (const float*)d_in[8];
    const float* in_w  = (const float*)d_in[9];
    const float* in_b  = (const float*)d_in[10];
    const float* out_w = (const float*)d_in[11];
    const float* out_b = (const float*)d_in[12];
    const float* ln_g  = (const float*)d_in[13];
    const float* ln_b  = (const float*)d_in[14];
    const float* l0_w  = (const float*)d_in[15];
    const float* l0_b  = (const float*)d_in[16];
    const float* l1_w  = (const float*)d_in[17];
    const float* l1_b  = (const float*)d_in[18];
    const float* lo_w  = (const float*)d_in[19];
    const float* lo_b  = (const float*)d_in[20];
    const float* pw    = (const float*)d_in[21];
    float* out = (float*)d_out;

    float *p_beff, *p_qkv, *p_inter, *p_x0, *p_x1, *p_qpool;
    __half *p_vh, *p_attnh, *p_interh, *p_Wqkvh, *p_Woh, *p_Wx0h;
    cudaGetSymbolAddress((void**)&p_beff,   g_beff);
    cudaGetSymbolAddress((void**)&p_qkv,    g_qkv);
    cudaGetSymbolAddress((void**)&p_inter,  g_inter);
    cudaGetSymbolAddress((void**)&p_x0,     g_x0);
    cudaGetSymbolAddress((void**)&p_x1,     g_x1);
    cudaGetSymbolAddress((void**)&p_qpool,  g_qpool);
    cudaGetSymbolAddress((void**)&p_vh,     g_vh);
    cudaGetSymbolAddress((void**)&p_attnh,  g_attnh);
    cudaGetSymbolAddress((void**)&p_interh, g_interh);
    cudaGetSymbolAddress((void**)&p_Wqkvh,  g_Wqkvh);
    cudaGetSymbolAddress((void**)&p_Woh,    g_Woh);
    cudaGetSymbolAddress((void**)&p_Wx0h,   g_Wx0h);

    // 1: split v_emb -> [hi|lo]
    asplit_kernel<<<NR_, 128>>>(v_emb, p_vh);
    // 2: fuse projection weights -> fp16 [hi|lo]
    fusew_kernel<<<dim3(16, 16, 3), dim3(16, 16)>>>(in_w, Wq, Wk, Wv, p_Wqkvh);
    // 3: fuse bias
    fuseb_kernel<<<3, 256>>>(in_w, in_b, bq, bk, bv, p_beff);
    // 4: QKV projection (HMMA)  <-- ncu captures launch #4
    gemm_mma<<<dim3(6, NR_/128), 256>>>(p_vh, p_Wqkvh, p_beff, p_qkv, 3*D_);
    // 5: attention
    attn_kernel<<<N_*H_, 64>>>(p_qkv, p_attnh);
    // 6: split out-proj weights
    wsplit_kernel<<<D_, 128>>>(out_w, p_Woh, D_);
    // 7: output projection
    gemm_mma<<<dim3(2, NR_/128), 256>>>(p_attnh, p_Woh, out_b, p_inter, D_);
    // 8: layernorm -> fp16 [hi|lo]
    ln_kernel<<<NR_, 256>>>(p_inter, ln_g, ln_b, p_interh);
    // 9: split x0 weights (640 rows, zero-padded past 600)
    wsplit_kernel<<<640, 128>>>(l0_w, p_Wx0h, MM_);
    // 10: x0 GEMM
    gemm_mma<<<dim3(5, NR_/128), 256>>>(p_interh, p_Wx0h, l0_b, p_x0, MM_);
    // 11-12: question pooling + x1
    qpool_kernel<<<N_, 256>>>(q_emb, p_qpool);
    sgemm_bt<<<dim3((MM_+127)/128, N_/128), 256>>>(p_qpool, l1_w, l1_b, p_x1, N_, MM_, D_);
    // 13: MLB finalize -> scores
    mlb_kernel<<<NR_/4, 128>>>(p_x0, p_x1, lo_w, lo_b, out);
    // 14: counter
    counter_kernel<<<N_, 128>>>(out, boxes, pw, out + NR_, out + NR_ + (size_t)N_*(OBJ_+1));
}

// round 17
// speedup vs baseline: 1.2979x; 1.0348x over previous
#include <cuda_runtime.h>
#include <cuda_fp16.h>
#include <math.h>
#include <stdint.h>

#define N_   1024
#define R_   100
#define D_   256
#define T_   14
#define H_   8
#define MM_  600
#define OBJ_ 36
#define PLN_ 16
#define DH_  32
#define NR_  (N_*R_)   /* 102400 */
#define KP2  512       /* stored split cols: [hi|lo]; compute K' = 768 via remap */
#define XCH  5         /* x0 column chunks of 128 */

// ---------------- scratch (device globals; no runtime allocation) ----------------
__device__ float g_beff[3*D_];
__device__ float g_qkv[(size_t)NR_*3*D_];
__device__ float g_inter[(size_t)NR_*D_];
__device__ float g_x1[(size_t)N_*MM_];
__device__ float g_qpool[(size_t)N_*D_];
__device__ float g_sabs[(size_t)NR_*XCH];
__device__ float g_sdot[(size_t)NR_*XCH];
__device__ __half g_vh[(size_t)NR_*KP2];
__device__ __half g_attnh[(size_t)NR_*KP2];
__device__ __half g_interh[(size_t)NR_*KP2];
__device__ __half g_Wqkvh[(size_t)(3*D_)*KP2];
__device__ __half g_Woh[(size_t)D_*KP2];
__device__ __half g_Wx0h[(size_t)640*KP2];

// ---------------- helpers ----------------
__device__ __forceinline__ float warpReduceSum(float v) {
    #pragma unroll
    for (int o = 16; o > 0; o >>= 1) v += __shfl_xor_sync(0xFFFFFFFFu, v, o);
    return v;
}

__device__ __forceinline__ uint32_t smem_u32(const void* p) {
    return (uint32_t)__cvta_generic_to_shared(p);
}

__device__ __forceinline__ void split_f16(float x, __half& hi, __half& lo) {
    hi = __float2half_rn(x);
    lo = __float2half_rn(x - __half2float(hi));
}

__device__ __forceinline__ void ldsm4(uint32_t* r, uint32_t addr) {
    asm volatile("ldmatrix.sync.aligned.m8n8.x4.shared.b16 {%0,%1,%2,%3}, [%4];"
                 : "=r"(r[0]), "=r"(r[1]), "=r"(r[2]), "=r"(r[3]) : "r"(addr));
}

__device__ __forceinline__ void mma16816(float* d, const uint32_t* a,
                                         uint32_t b0, uint32_t b1) {
    asm volatile(
        "mma.sync.aligned.m16n8k16.row.col.f32.f16.f16.f32 "
        "{%0,%1,%2,%3}, {%4,%5,%6,%7}, {%8,%9}, {%0,%1,%2,%3};"
        : "+f"(d[0]), "+f"(d[1]), "+f"(d[2]), "+f"(d[3])
        : "r"(a[0]), "r"(a[1]), "r"(a[2]), "r"(a[3]), "r"(b0), "r"(b1));
}

// k-block (32 cols each) -> stored offset in halves.
// Compute order: kb 0-7 = a_hi*w_hi, kb 8-15 = a_hi*w_lo, kb 16-23 = a_lo*w_hi.
__device__ __forceinline__ int aoff(int kb) {
    return (((kb >> 3) == 2) ? 256 : 0) + (kb & 7) * 32;
}
__device__ __forceinline__ int boff(int kb) {
    return (((kb >> 3) == 1) ? 256 : 0) + (kb & 7) * 32;
}

// ---------------- weight fusion: Weff = in_w_part @ W_part -> fp16 [hi|lo] -------
__global__ void fusew_kernel(const float* __restrict__ in_w,
                             const float* __restrict__ Wq,
                             const float* __restrict__ Wk,
                             const float* __restrict__ Wv,
                             __half* __restrict__ Wh) {
    int p = blockIdx.z;
    const float* W = (p == 0) ? Wq : ((p == 1) ? Wk : Wv);
    __shared__ float Ai[16][16];
    __shared__ float Bi[16][17];
    int tx = threadIdx.x, ty = threadIdx.y;
    int o = blockIdx.y * 16 + ty;
    int k = blockIdx.x * 16 + tx;
    float acc = 0.f;
    for (int j0 = 0; j0 < D_; j0 += 16) {
        Ai[ty][tx] = in_w[(size_t)(p*D_ + o)*D_ + j0 + tx];
        Bi[ty][tx] = W[(size_t)(j0 + ty)*D_ + k];
        __syncthreads();
        #pragma unroll
        for (int jj = 0; jj < 16; jj++) acc += Ai[ty][jj] * Bi[jj][tx];
        __syncthreads();
    }
    __half hi, lo;
    split_f16(acc, hi, lo);
    __half* yr = Wh + (size_t)(p*D_ + o) * KP2;
    yr[k] = hi; yr[D_ + k] = lo;
}

__global__ void fuseb_kernel(const float* __restrict__ in_w,
                             const float* __restrict__ in_b,
                             const float* __restrict__ bq,
                             const float* __restrict__ bk,
                             const float* __restrict__ bv,
                             float* __restrict__ beff) {
    int o = blockIdx.x * blockDim.x + threadIdx.x;
    if (o >= 3*D_) return;
    int p = o / D_;
    const float* bb = (p == 0) ? bq : ((p == 1) ? bk : bv);
    const float* wrow = in_w + (size_t)o * D_;
    float s = in_b[o];
    for (int j = 0; j < D_; j++) s += wrow[j] * bb[j];
    beff[o] = s;
}

// ---------------- activation split: [hi|lo] ----------------
__global__ __launch_bounds__(128) void asplit_kernel(const float* __restrict__ X,
                                                     __half* __restrict__ Y) {
    size_t row = blockIdx.x;
    int k = threadIdx.x * 2;
    float2 v = *(const float2*)(X + row * D_ + k);
    __half h0, l0, h1, l1;
    split_f16(v.x, h0, l0);
    split_f16(v.y, h1, l1);
    __half2 hp; hp.x = h0; hp.y = h1;
    __half2 lp; lp.x = l0; lp.y = l1;
    __half2* yr = (__half2*)(Y + row * KP2);
    int o = k >> 1;
    yr[o] = hp;
    yr[(D_ >> 1) + o] = lp;
}

// ---------------- weight split: [hi|lo] ----------------
__global__ __launch_bounds__(128) void wsplit_kernel(const float* __restrict__ W,
                                                     __half* __restrict__ Y, int Nc) {
    int r = blockIdx.x;
    int k = threadIdx.x * 2;
    float2 v = make_float2(0.f, 0.f);
    if (r < Nc) v = *(const float2*)(W + (size_t)r * D_ + k);
    __half h0, l0, h1, l1;
    split_f16(v.x, h0, l0);
    split_f16(v.y, h1, l1);
    __half2 hp; hp.x = h0; hp.y = h1;
    __half2 lp; lp.x = l0; lp.y = l1;
    __half2* yr = (__half2*)(Y + (size_t)r * KP2);
    int o = k >> 1;
    yr[o] = hp;
    yr[(D_ >> 1) + o] = lp;
}

// ---------------- HMMA GEMM: C[M,Nc] f32 = split-A * split-B^T + bias ------------
// 128x128 tile, BK=32, 256 threads (8 warps as 2m x 4n, 64x32 per warp),
// register-staged double buffer, 24 logical k-blocks over stored 512 cols.
#define SROW 40   /* padded row stride in halves (80 B) */

__global__ __launch_bounds__(256, 2) void gemm_mma(const __half* __restrict__ A,
                                                   const __half* __restrict__ B,
                                                   const float* __restrict__ bias,
                                                   float* __restrict__ C, int Nc) {
    __shared__ __half sA[2][128*SROW];
    __shared__ __half sB[2][128*SROW];
    int tid = threadIdx.x;
    int wid = tid >> 5, lane = tid & 31;
    int wm = wid & 1, wn = wid >> 1;
    int m0 = blockIdx.y * 128, n0 = blockIdx.x * 128;

    int lrow = tid >> 1;
    int lpart = (tid & 1) * 16;
    const __half* Agb = A + (size_t)(m0 + lrow) * KP2 + lpart;
    const __half* Bgb = B + (size_t)(n0 + lrow) * KP2 + lpart;

    float acc[4][4][4];
    #pragma unroll
    for (int i = 0; i < 4; i++)
        #pragma unroll
        for (int j = 0; j < 4; j++)
            #pragma unroll
            for (int q = 0; q < 4; q++) acc[i][j][q] = 0.f;

    uint4 ra0, ra1, rb0, rb1;
    ra0 = *(const uint4*)(Agb);
    ra1 = *(const uint4*)(Agb + 8);
    rb0 = *(const uint4*)(Bgb);
    rb1 = *(const uint4*)(Bgb + 8);
    *(uint4*)&sA[0][lrow*SROW + lpart]     = ra0;
    *(uint4*)&sA[0][lrow*SROW + lpart + 8] = ra1;
    *(uint4*)&sB[0][lrow*SROW + lpart]     = rb0;
    *(uint4*)&sB[0][lrow*SROW + lpart + 8] = rb1;
    __syncthreads();

    int arow = wm*64 + (lane & 15);
    int brow = wn*32 + (lane & 15);
    int colb = (lane >> 4) * 8;

    for (int kb = 0; kb < 24; kb++) {
        bool hn = (kb < 23);
        if (hn) {
            const __half* An = Agb + aoff(kb + 1);
            const __half* Bn = Bgb + boff(kb + 1);
            ra0 = *(const uint4*)(An);
            ra1 = *(const uint4*)(An + 8);
            rb0 = *(const uint4*)(Bn);
            rb1 = *(const uint4*)(Bn + 8);
        }
        int bf = kb & 1;
        #pragma unroll
        for (int ks = 0; ks < 2; ks++) {
            uint32_t af[4][4], bfr[2][4];
            #pragma unroll
            for (int mi = 0; mi < 4; mi++)
                ldsm4(af[mi], smem_u32(&sA[bf][(arow + mi*16)*SROW + ks*16 + colb]));
            #pragma unroll
            for (int ni = 0; ni < 2; ni++)
                ldsm4(bfr[ni], smem_u32(&sB[bf][(brow + ni*16)*SROW + ks*16 + colb]));
            #pragma unroll
            for (int mi = 0; mi < 4; mi++) {
                #pragma unroll
                for (int ni = 0; ni < 2; ni++) {
                    mma16816(acc[mi][2*ni],   af[mi], bfr[ni][0], bfr[ni][2]);
                    mma16816(acc[mi][2*ni+1], af[mi], bfr[ni][1], bfr[ni][3]);
                }
            }
        }
        if (hn) {
            int nb = bf ^ 1;
            *(uint4*)&sA[nb][lrow*SROW + lpart]     = ra0;
            *(uint4*)&sA[nb][lrow*SROW + lpart + 8] = ra1;
            *(uint4*)&sB[nb][lrow*SROW + lpart]     = rb0;
            *(uint4*)&sB[nb][lrow*SROW + lpart + 8] = rb1;
            __syncthreads();
        }
    }

    int rbase = m0 + wm*64 + (lane >> 2);
    int cbase = n0 + wn*32 + (lane & 3)*2;
    #pragma unroll
    for (int mi = 0; mi < 4; mi++) {
        #pragma unroll
        for (int nj = 0; nj < 4; nj++) {
            int r = rbase + mi*16;
            int c = cbase + nj*8;
            if (c < Nc) {
                float b0v = bias[c];
                C[(size_t)r * Nc + c]       = acc[mi][nj][0] + b0v;
                C[(size_t)(r+8) * Nc + c]   = acc[mi][nj][2] + b0v;
            }
            if (c + 1 < Nc) {
                float b1v = bias[c+1];
                C[(size_t)r * Nc + c + 1]     = acc[mi][nj][1] + b1v;
                C[(size_t)(r+8) * Nc + c + 1] = acc[mi][nj][3] + b1v;
            }
        }
    }
}

// ---------------- x0 GEMM with fused MLB partial reduction ----------------
// Same mainloop as gemm_mma; epilogue computes per-row partial (s_abs, s_dot)
// over this CTA's 128 columns and stores to g_sabs/g_sdot[row*XCH + chunk].
// x0 itself is never materialized.
__global__ __launch_bounds__(256, 2) void gemm_x0(const __half* __restrict__ A,
                                                  const __half* __restrict__ B,
                                                  const float* __restrict__ l0_b,
                                                  const float* __restrict__ x1,
                                                  const float* __restrict__ lo_w,
                                                  float* __restrict__ sabs_out,
                                                  float* __restrict__ sdot_out) {
    __shared__ __half sA[2][128*SROW];
    __shared__ __half sB[2][128*SROW];
    __shared__ float spA[128][4];
    __shared__ float spD[128][4];
    int tid = threadIdx.x;
    int wid = tid >> 5, lane = tid & 31;
    int wm = wid & 1, wn = wid >> 1;
    int m0 = blockIdx.y * 128, n0 = blockIdx.x * 128;

    int lrow = tid >> 1;
    int lpart = (tid & 1) * 16;
    const __half* Agb = A + (size_t)(m0 + lrow) * KP2 + lpart;
    const __half* Bgb = B + (size_t)(n0 + lrow) * KP2 + lpart;

    float acc[4][4][4];
    #pragma unroll
    for (int i = 0; i < 4; i++)
        #pragma unroll
        for (int j = 0; j < 4; j++)
            #pragma unroll
            for (int q = 0; q < 4; q++) acc[i][j][q] = 0.f;

    uint4 ra0, ra1, rb0, rb1;
    ra0 = *(const uint4*)(Agb);
    ra1 = *(const uint4*)(Agb + 8);
    rb0 = *(const uint4*)(Bgb);
    rb1 = *(const uint4*)(Bgb + 8);
    *(uint4*)&sA[0][lrow*SROW + lpart]     = ra0;
    *(uint4*)&sA[0][lrow*SROW + lpart + 8] = ra1;
    *(uint4*)&sB[0][lrow*SROW + lpart]     = rb0;
    *(uint4*)&sB[0][lrow*SROW + lpart + 8] = rb1;
    __syncthreads();

    int arow = wm*64 + (lane & 15);
    int brow = wn*32 + (lane & 15);
    int colb = (lane >> 4) * 8;

    for (int kb = 0; kb < 24; kb++) {
        bool hn = (kb < 23);
        if (hn) {
            const __half* An = Agb + aoff(kb + 1);
            const __half* Bn = Bgb + boff(kb + 1);
            ra0 = *(const uint4*)(An);
            ra1 = *(const uint4*)(An + 8);
            rb0 = *(const uint4*)(Bn);
            rb1 = *(const uint4*)(Bn + 8);
        }
        int bf = kb & 1;
        #pragma unroll
        for (int ks = 0; ks < 2; ks++) {
            uint32_t af[4][4], bfr[2][4];
            #pragma unroll
            for (int mi = 0; mi < 4; mi++)
                ldsm4(af[mi], smem_u32(&sA[bf][(arow + mi*16)*SROW + ks*16 + colb]));
            #pragma unroll
            for (int ni = 0; ni < 2; ni++)
                ldsm4(bfr[ni], smem_u32(&sB[bf][(brow + ni*16)*SROW + ks*16 + colb]));
            #pragma unroll
            for (int mi = 0; mi < 4; mi++) {
                #pragma unroll
                for (int ni = 0; ni < 2; ni++) {
                    mma16816(acc[mi][2*ni],   af[mi], bfr[ni][0], bfr[ni][2]);
                    mma16816(acc[mi][2*ni+1], af[mi], bfr[ni][1], bfr[ni][3]);
                }
            }
        }
        if (hn) {
            int nb = bf ^ 1;
            *(uint4*)&sA[nb][lrow*SROW + lpart]     = ra0;
            *(uint4*)&sA[nb][lrow*SROW + lpart + 8] = ra1;
            *(uint4*)&sB[nb][lrow*SROW + lpart]     = rb0;
            *(uint4*)&sB[nb][lrow*SROW + lpart + 8] = rb1;
            __syncthreads();
        }
    }
    __syncthreads();  // smem reuse barrier before partial-sum stores

    // epilogue: per-row MLB partials over this CTA's 128 cols
    int cbase = n0 + wn*32 + (lane & 3)*2;
    #pragma unroll
    for (int mi = 0; mi < 4; mi++) {
        #pragma unroll
        for (int h = 0; h < 2; h++) {
            int trow = wm*64 + mi*16 + (lane >> 2) + 8*h;
            int grow = m0 + trow;
            int nb = grow / R_;
            const float* x1r = x1 + (size_t)nb * MM_;
            float sabs = 0.f, sdot = 0.f;
            #pragma unroll
            for (int nj = 0; nj < 4; nj++) {
                #pragma unroll
                for (int e = 0; e < 2; e++) {
                    int col = cbase + nj*8 + e;
                    if (col < MM_) {
                        float xv = acc[mi][nj][h*2 + e] + l0_b[col];
                        float z = xv * x1r[col];
                        float az = fabsf(z);
                        sabs += az;
                        sdot += copysignf(sqrtf(az), z) * lo_w[col];
                    }
                }
            }
            // reduce over the 4 lane-groups (lane&3)
            sabs += __shfl_xor_sync(0xFFFFFFFFu, sabs, 1);
            sabs += __shfl_xor_sync(0xFFFFFFFFu, sabs, 2);
            sdot += __shfl_xor_sync(0xFFFFFFFFu, sdot, 1);
            sdot += __shfl_xor_sync(0xFFFFFFFFu, sdot, 2);
            if ((lane & 3) == 0) {
                spA[trow][wn] = sabs;
                spD[trow][wn] = sdot;
            }
        }
    }
    __syncthreads();
    if (tid < 128) {
        float sa = spA[tid][0] + spA[tid][1] + spA[tid][2] + spA[tid][3];
        float sd = spD[tid][0] + spD[tid][1] + spD[tid][2] + spD[tid][3];
        size_t grow = (size_t)(m0 + tid);
        sabs_out[grow * XCH + blockIdx.x] = sa;
        sdot_out[grow * XCH + blockIdx.x] = sd;
    }
}

// ---------------- MLB finalize: combine per-chunk partials ----------------
__global__ __launch_bounds__(256) void mlbfin_kernel(const float* __restrict__ sabs5,
                                                     const float* __restrict__ sdot5,
                                                     const float* __restrict__ lo_b,
                                                     float* __restrict__ scores) {
    int nr = blockIdx.x * 256 + threadIdx.x;
    if (nr >= NR_) return;
    float sa = 0.f, sd = 0.f;
    #pragma unroll
    for (int c = 0; c < XCH; c++) {
        sa += sabs5[(size_t)nr * XCH + c];
        sd += sdot5[(size_t)nr * XCH + c];
    }
    float nrm = fmaxf(sqrtf(sa), 1e-12f);
    float val = sd / nrm + lo_b[0];
    scores[nr] = 1.f / (1.f + __expf(-val));
}

// ---------------- SIMT SGEMM (tiny x1) ----------------
__global__ __launch_bounds__(256) void sgemm_bt(const float* __restrict__ A,
                                                const float* __restrict__ B,
                                                const float* __restrict__ bias,
                                                float* __restrict__ C,
                                                int M, int Nc, int K) {
    __shared__ float As[2][16][128];
    __shared__ float Bs[2][16][128];
    int tid = threadIdx.x;
    int tcol = tid & 15, trow = tid >> 4;
    int lRow = tid >> 1;
    int lCol = (tid & 1) * 8;
    const float* Ab = A + ((size_t)blockIdx.y * 128 + lRow) * K + lCol;
    int bRowG = blockIdx.x * 128 + lRow;
    const float* Bb = B + (size_t)bRowG * K + lCol;
    bool bvalid = (bRowG < Nc);

    float acc[8][8];
    #pragma unroll
    for (int i = 0; i < 8; i++)
        #pragma unroll
        for (int j = 0; j < 8; j++) acc[i][j] = 0.f;

    float4 a0, a1, b0, b1;
    const float4 z4 = make_float4(0.f, 0.f, 0.f, 0.f);
    a0 = *(const float4*)(Ab);
    a1 = *(const float4*)(Ab + 4);
    b0 = bvalid ? *(const float4*)(Bb)     : z4;
    b1 = bvalid ? *(const float4*)(Bb + 4) : z4;
    As[0][lCol+0][lRow] = a0.x; As[0][lCol+1][lRow] = a0.y;
    As[0][lCol+2][lRow] = a0.z; As[0][lCol+3][lRow] = a0.w;
    As[0][lCol+4][lRow] = a1.x; As[0][lCol+5][lRow] = a1.y;
    As[0][lCol+6][lRow] = a1.z; As[0][lCol+7][lRow] = a1.w;
    Bs[0][lCol+0][lRow] = b0.x; Bs[0][lCol+1][lRow] = b0.y;
    Bs[0][lCol+2][lRow] = b0.z; Bs[0][lCol+3][lRow] = b0.w;
    Bs[0][lCol+4][lRow] = b1.x; Bs[0][lCol+5][lRow] = b1.y;
    Bs[0][lCol+6][lRow] = b1.z; Bs[0][lCol+7][lRow] = b1.w;
    __syncthreads();

    int buf = 0;
    for (int k0 = 0; k0 < K; k0 += 16) {
        bool hn = (k0 + 16 < K);
        if (hn) {
            a0 = *(const float4*)(Ab + k0 + 16);
            a1 = *(const float4*)(Ab + k0 + 20);
            b0 = bvalid ? *(const float4*)(Bb + k0 + 16) : z4;
            b1 = bvalid ? *(const float4*)(Bb + k0 + 20) : z4;
        }
        #pragma unroll
        for (int kk = 0; kk < 16; kk++) {
            float ar[8], br[8];
            *(float4*)(ar)     = *(const float4*)&As[buf][kk][trow*8];
            *(float4*)(ar + 4) = *(const float4*)&As[buf][kk][trow*8 + 4];
            *(float4*)(br)     = *(const float4*)&Bs[buf][kk][tcol*8];
            *(float4*)(br + 4) = *(const float4*)&Bs[buf][kk][tcol*8 + 4];
            #pragma unroll
            for (int i = 0; i < 8; i++)
                #pragma unroll
                for (int j = 0; j < 8; j++) acc[i][j] += ar[i] * br[j];
        }
        if (hn) {
            int nb = buf ^ 1;
            As[nb][lCol+0][lRow] = a0.x; As[nb][lCol+1][lRow] = a0.y;
            As[nb][lCol+2][lRow] = a0.z; As[nb][lCol+3][lRow] = a0.w;
            As[nb][lCol+4][lRow] = a1.x; As[nb][lCol+5][lRow] = a1.y;
            As[nb][lCol+6][lRow] = a1.z; As[nb][lCol+7][lRow] = a1.w;
            Bs[nb][lCol+0][lRow] = b0.x; Bs[nb][lCol+1][lRow] = b0.y;
            Bs[nb][lCol+2][lRow] = b0.z; Bs[nb][lCol+3][lRow] = b0.w;
            Bs[nb][lCol+4][lRow] = b1.x; Bs[nb][lCol+5][lRow] = b1.y;
            Bs[nb][lCol+6][lRow] = b1.z; Bs[nb][lCol+7][lRow] = b1.w;
            __syncthreads();
            buf = nb;
        }
    }

    int rb = blockIdx.y * 128 + trow * 8;
    int cb = blockIdx.x * 128 + tcol * 8;
    for (int i = 0; i < 8; i++) {
        size_t ro = (size_t)(rb + i) * Nc;
        #pragma unroll
        for (int j = 0; j < 8; j++) {
            int c = cb + j;
            if (c < Nc) C[ro + c] = acc[i][j] + bias[c];
        }
    }
}

// ---------------- attention: per (n,h); writes fp16 [hi|lo] split ----------------
__global__ __launch_bounds__(64) void attn_kernel(const float* __restrict__ qkv,
                                                  __half* __restrict__ outh) {
    __shared__ float Ks[R_][DH_];
    __shared__ float Vs[R_][DH_];
    int b = blockIdx.x;
    int n = b >> 3, h = b & 7;
    const float* base = qkv + (size_t)n * R_ * (3*D_) + h * DH_;
    for (int t = threadIdx.x; t < R_ * 8; t += 64) {
        int r = t >> 3, c = (t & 7) * 4;
        const float* p = base + (size_t)r * (3*D_) + c;
        *(float4*)&Ks[r][c] = *(const float4*)(p + D_);
        *(float4*)&Vs[r][c] = *(const float4*)(p + 2*D_);
    }
    __syncthreads();

    int t = threadIdx.x;
    if (t < 50) {
        const float scale = 0.17677669529663687f;  // 1/sqrt(32)
        int r0 = t, r1 = t + 50;
        float q0[DH_], q1[DH_];
        const float* p0 = base + (size_t)r0 * (3*D_);
        const float* p1 = base + (size_t)r1 * (3*D_);
        #pragma unroll
        for (int d = 0; d < DH_; d += 4) {
            float4 v0 = *(const float4*)(p0 + d);
            float4 v1 = *(const float4*)(p1 + d);
            q0[d+0] = v0.x * scale; q0[d+1] = v0.y * scale;
            q0[d+2] = v0.z * scale; q0[d+3] = v0.w * scale;
            q1[d+0] = v1.x * scale; q1[d+1] = v1.y * scale;
            q1[d+2] = v1.z * scale; q1[d+3] = v1.w * scale;
        }
        float acc0[DH_], acc1[DH_];
        #pragma unroll
        for (int d = 0; d < DH_; d++) { acc0[d] = 0.f; acc1[d] = 0.f; }
        float s0 = 0.f, s1 = 0.f;
        for (int k = 0; k < R_; k++) {
            float d0 = 0.f, d1 = 0.f;
            #pragma unroll
            for (int d = 0; d < DH_; d++) {
                float kv = Ks[k][d];
                d0 += q0[d] * kv;
                d1 += q1[d] * kv;
            }
            float w0 = __expf(d0), w1 = __expf(d1);
            s0 += w0; s1 += w1;
            #pragma unroll
            for (int d = 0; d < DH_; d++) {
                float vv = Vs[k][d];
                acc0[d] += w0 * vv;
                acc1[d] += w1 * vv;
            }
        }
        float i0 = 1.f / s0, i1 = 1.f / s1;
        __half2* ob0 = (__half2*)(outh + (size_t)(n * R_ + r0) * KP2 + h * DH_);
        __half2* ob1 = (__half2*)(outh + (size_t)(n * R_ + r1) * KP2 + h * DH_);
        #pragma unroll
        for (int d = 0; d < DH_; d += 2) {
            float xa = acc0[d] * i0, xb = acc0[d+1] * i0;
            float ya = acc1[d] * i1, yb = acc1[d+1] * i1;
            __half ha0, la0, hb0, lb0, ha1, la1, hb1, lb1;
            split_f16(xa, ha0, la0); split_f16(xb, hb0, lb0);
            split_f16(ya, ha1, la1); split_f16(yb, hb1, lb1);
            __half2 h2a; h2a.x = ha0; h2a.y = hb0;
            __half2 l2a; l2a.x = la0; l2a.y = lb0;
            __half2 h2b; h2b.x = ha1; h2b.y = hb1;
            __half2 l2b; l2b.x = la1; l2b.y = lb1;
            int o = d >> 1;
            ob0[o] = h2a; ob0[(D_ >> 1) + o] = l2a;
            ob1[o] = h2b; ob1[(D_ >> 1) + o] = l2b;
        }
    }
}

// ---------------- layernorm: fp32 in, fp16 [hi|lo] out (shuffle reductions) ------
__global__ __launch_bounds__(256) void ln_kernel(const float* __restrict__ X,
                                                 const float* __restrict__ g,
                                                 const float* __restrict__ b,
                                                 __half* __restrict__ Yh) {
    __shared__ float part[8];
    __shared__ float bcast;
    int row = blockIdx.x, t = threadIdx.x;
    int w = t >> 5, lane = t & 31;
    float v = X[(size_t)row * D_ + t];

    float s = warpReduceSum(v);
    if (lane == 0) part[w] = s;
    __syncthreads();
    if (t == 0) {
        float tot = 0.f;
        #pragma unroll
        for (int i = 0; i < 8; i++) tot += part[i];
        bcast = tot * (1.f / D_);
    }
    __syncthreads();
    float mu = bcast;
    float d = v - mu;

    float s2 = warpReduceSum(d * d);
    if (lane == 0) part[w] = s2;
    __syncthreads();
    if (t == 0) {
        float tot = 0.f;
        #pragma unroll
        for (int i = 0; i < 8; i++) tot += part[i];
        bcast = tot * (1.f / D_);
    }
    __syncthreads();
    float var = bcast;

    float y = d * rsqrtf(var + 1e-5f) * g[t] + b[t];
    __half hi, lo;
    split_f16(y, hi, lo);
    __half* yr = Yh + (size_t)row * KP2;
    yr[t] = hi; yr[D_ + t] = lo;
}

// ---------------- question pool ----------------
__global__ void qpool_kernel(const float* __restrict__ q_emb, float* __restrict__ qp) {
    int n = blockIdx.x, d = threadIdx.x;
    float s = 0.f;
    for (int tt = 0; tt < T_; tt++) s += q_emb[((size_t)n * T_ + tt) * D_ + d];
    qp[(size_t)n * D_ + d] = s * (1.f / T_);
}

// ---------------- counter (256 threads) ----------------
__device__ __forceinline__ float plin2(const float* __restrict__ w,
                                       const float* __restrict__ c, float x) {
    float y = 16.f * __saturatef(x);
    float fl = floorf(y);
    int i = (int)fl; if (i > 16) i = 16; if (i < 0) i = 0;
    float fr = y - fl;
    int i1 = i + 1; if (i1 > 16) i1 = 16;
    return c[i] + fr * w[i1];
}

__global__ __launch_bounds__(256) void counter_kernel(const float* __restrict__ scores,
                                                      const float* __restrict__ boxes,
                                                      const float* __restrict__ pw,
                                                      float* __restrict__ pred,
                                                      float* __restrict__ confp) {
    __shared__ float satt[R_];
    __shared__ int   selidx[OBJ_];
    __shared__ float pwW[8][PLN_+1], pwC[8][PLN_+1];
    __shared__ float att_top[OBJ_], bx[OBJ_][4], area[OBJ_];
    __shared__ float dist[OBJ_][OBJ_], dsc[OBJ_][OBJ_], scm[OBJ_][OBJ_], simm[OBJ_][OBJ_];
    __shared__ float rs[OBJ_];
    __shared__ float red[16];
    __shared__ float bc[3];

    int n = blockIdx.x, t = threadIdx.x;
    if (t < R_) satt[t] = scores[(size_t)n * R_ + t];
    if (t < 8) {
        float tmp[PLN_+1]; float sum = 0.f;
        for (int j = 0; j <= PLN_; j++) {
            float a = fabsf(pw[t*(PLN_+1) + j]);
            if (j == 0) a = 0.f;
            tmp[j] = a; sum += a;
        }
        float inv = 1.f / sum, c = 0.f;
        for (int j = 0; j <= PLN_; j++) {
            float wj = tmp[j] * inv;
            pwW[t][j] = wj; c += wj; pwC[t][j] = c;
        }
    }
    __syncthreads();

    // rank-based top-36 (identical set/ordering as iterative argmax)
    if (t < R_) {
        float v = satt[t];
        int rank = 0;
        #pragma unroll 4
        for (int j = 0; j < R_; j++) {
            float u = satt[j];
            rank += (u > v) || (u == v && j < t);
        }
        if (rank < OBJ_) {
            att_top[rank] = v;
            selidx[rank] = t;
        }
    }
    __syncthreads();

    if (t < OBJ_) {
        const float* bp = boxes + ((size_t)n * R_ + selidx[t]) * 4;
        float x1v = bp[0], y1v = bp[1], x2v = bp[2], y2v = bp[3];
        bx[t][0] = x1v; bx[t][1] = y1v; bx[t][2] = x2v; bx[t][3] = y2v;
        area[t] = fmaxf(x2v - x1v, 0.f) * fmaxf(y2v - y1v, 0.f);
    }
    __syncthreads();

    for (int u = t; u < OBJ_*OBJ_; u += 256) {
        int j = u / OBJ_, k = u % OBJ_;
        float xx1 = fmaxf(bx[j][0], bx[k][0]), yy1 = fmaxf(bx[j][1], bx[k][1]);
        float xx2 = fminf(bx[j][2], bx[k][2]), yy2 = fminf(bx[j][3], bx[k][3]);
        float iw = fmaxf(xx2-xx1, 0.f), ih = fmaxf(yy2-yy1, 0.f);
        float inter = iw * ih;
        float iou = inter / (area[j] + area[k] - inter + 1e-12f);
        float dd = 1.f - iou;
        dist[j][k] = dd;
        float rel = att_top[j] * att_top[k];
        scm[j][k] = plin2(pwW[0], pwC[0], rel) * plin2(pwW[1], pwC[1], dd);
        dsc[j][k] = plin2(pwW[3], pwC[3], rel) * plin2(pwW[4], pwC[4], dd);
    }
    __syncthreads();

    for (int u = t; u < OBJ_*OBJ_; u += 256) {
        int j = u / OBJ_, k = u % OBJ_;
        float p = plin2(pwW[2], pwC[2], 1.f - fabsf(att_top[j] - att_top[k]));
        #pragma unroll 4
        for (int i = 0; i < OBJ_; i++)
            p *= plin2(pwW[2], pwC[2], 1.f - fabsf(dsc[i][j] - dsc[i][k]));
        simm[j][k] = p;
    }
    __syncthreads();

    if (t < OBJ_) {
        float s = 0.f;
        for (int k = 0; k < OBJ_; k++) s += simm[t][k];
        rs[t] = s;
    }
    __syncthreads();

    float loc_tot = 0.f, loc_conf = 0.f;
    for (int u = t; u < OBJ_*OBJ_; u += 256) {
        int j = u / OBJ_, k = u % OBJ_;
        loc_tot  += scm[j][k] / (rs[j] * rs[k]);
        loc_conf += fabsf(plin2(pwW[6], pwC[6], dist[j][k]) - 0.5f) * (1.f / (OBJ_*OBJ_));
    }
    if (t < OBJ_) {
        float a = att_top[t];
        loc_tot  += plin2(pwW[0], pwC[0], a*a) / rs[t];
        loc_conf += fabsf(plin2(pwW[5], pwC[5], a) - 0.5f) * (1.f / OBJ_);
    }
    {
        int w = t >> 5, lane = t & 31;
        loc_tot  = warpReduceSum(loc_tot);
        loc_conf = warpReduceSum(loc_conf);
        if (lane == 0) { red[w] = loc_tot; red[8 + w] = loc_conf; }
        __syncthreads();
        if (t == 0) {
            loc_tot = 0.f; loc_conf = 0.f;
            #pragma unroll
            for (int i = 0; i < 8; i++) { loc_tot += red[i]; loc_conf += red[8 + i]; }
            float total = sqrtf(loc_tot + 1e-20f);
            float conf = plin2(pwW[7], pwC[7], loc_conf);
            confp[n] = conf;
            float s = fminf(fmaxf(total, 0.f), (float)OBJ_);
            float fl = floorf(s);
            int i = (int)fl; if (i > OBJ_) i = OBJ_; if (i < 0) i = 0;
            bc[0] = conf; bc[1] = s - fl; bc[2] = __int_as_float(i);
        }
    }
    __syncthreads();
    if (t <= OBJ_) {
        float conf = bc[0], f = bc[1];
        int i = __float_as_int(bc[2]);
        int i1 = i + 1; if (i1 > OBJ_) i1 = OBJ_;
        float v = 0.f;
        if (t == i)  v += 1.f - f;
        if (t == i1) v += f;
        pred[(size_t)n * (OBJ_+1) + t] = conf * v;
    }
}

// ---------------- launch ----------------
extern "C" void kernel_launch(void* const* d_in, const int* in_sizes, int n_in,
                              void* d_out, int out_size) {
    const float* v_emb = (const float*)d_in[0];
    const float* q_emb = (const float*)d_in[1];
    const float* boxes = (const float*)d_in[2];
    const float* Wq    = (const float*)d_in[3];
    const float* bq    = (const float*)d_in[4];
    const float* Wk    = (const float*)d_in[5];
    const float* bk    = (const float*)d_in[6];
    const float* Wv    = (const float*)d_in[7];
    const float* bv    = (const float*)d_in[8];
    const float* in_w  = (const float*)d_in[9];
    const float* in_b  = (const float*)d_in[10];
    const float* out_w = (const float*)d_in[11];
    const float* out_b = (const float*)d_in[12];
    const float* ln_g  = (const float*)d_in[13];
    const float* ln_b  = (const float*)d_in[14];
    const float* l0_w  = (const float*)d_in[15];
    const float* l0_b  = (const float*)d_in[16];
    const float* l1_w  = (const float*)d_in[17];
    const float* l1_b  = (const float*)d_in[18];
    const float* lo_w  = (const float*)d_in[19];
    const float* lo_b  = (const float*)d_in[20];
    const float* pw    = (const float*)d_in[21];
    float* out = (float*)d_out;

    float *p_beff, *p_qkv, *p_inter, *p_x1, *p_qpool, *p_sabs, *p_sdot;
    __half *p_vh, *p_attnh, *p_interh, *p_Wqkvh, *p_Woh, *p_Wx0h;
    cudaGetSymbolAddress((void**)&p_beff,   g_beff);
    cudaGetSymbolAddress((void**)&p_qkv,    g_qkv);
    cudaGetSymbolAddress((void**)&p_inter,  g_inter);
    cudaGetSymbolAddress((void**)&p_x1,     g_x1);
    cudaGetSymbolAddress((void**)&p_qpool,  g_qpool);
    cudaGetSymbolAddress((void**)&p_sabs,   g_sabs);
    cudaGetSymbolAddress((void**)&p_sdot,   g_sdot);
    cudaGetSymbolAddress((void**)&p_vh,     g_vh);
    cudaGetSymbolAddress((void**)&p_attnh,  g_attnh);
    cudaGetSymbolAddress((void**)&p_interh, g_interh);
    cudaGetSymbolAddress((void**)&p_Wqkvh,  g_Wqkvh);
    cudaGetSymbolAddress((void**)&p_Woh,    g_Woh);
    cudaGetSymbolAddress((void**)&p_Wx0h,   g_Wx0h);

    // 1: split v_emb -> [hi|lo]
    asplit_kernel<<<NR_, 128>>>(v_emb, p_vh);
    // 2: fuse projection weights -> fp16 [hi|lo]
    fusew_kernel<<<dim3(16, 16, 3), dim3(16, 16)>>>(in_w, Wq, Wk, Wv, p_Wqkvh);
    // 3: fuse bias
    fuseb_kernel<<<3, 256>>>(in_w, in_b, bq, bk, bv, p_beff);
    // 4: QKV projection (HMMA)  <-- ncu captures launch #4
    gemm_mma<<<dim3(6, NR_/128), 256>>>(p_vh, p_Wqkvh, p_beff, p_qkv, 3*D_);
    // 5: attention
    attn_kernel<<<N_*H_, 64>>>(p_qkv, p_attnh);
    // 6: split out-proj weights
    wsplit_kernel<<<D_, 128>>>(out_w, p_Woh, D_);
    // 7: output projection
    gemm_mma<<<dim3(2, NR_/128), 256>>>(p_attnh, p_Woh, out_b, p_inter, D_);
    // 8: layernorm -> fp16 [hi|lo]
    ln_kernel<<<NR_, 256>>>(p_inter, ln_g, ln_b, p_interh);
    // 9: split x0 weights (640 rows, zero-padded past 600)
    wsplit_kernel<<<640, 128>>>(l0_w, p_Wx0h, MM_);
    // 10-11: question pooling + x1 (needed by fused x0 epilogue)
    qpool_kernel<<<N_, 256>>>(q_emb, p_qpool);
    sgemm_bt<<<dim3((MM_+127)/128, N_/128), 256>>>(p_qpool, l1_w, l1_b, p_x1, N_, MM_, D_);
    // 12: x0 GEMM with fused MLB partial reduction (x0 never materialized)
    gemm_x0<<<dim3(XCH, NR_/128), 256>>>(p_interh, p_Wx0h, l0_b, p_x1, lo_w,
                                         p_sabs, p_sdot);
    // 13: MLB finalize -> scores at d_out[0 : NR)
    mlbfin_kernel<<<(NR_ + 255)/256, 256>>>(p_sabs, p_sdot, lo_b, out);
    // 14: counter
    counter_kernel<<<N_, 256>>>(out, boxes, pw, out + NR_, out + NR_ + (size_t)N_*(OBJ_+1));
}